// round 1
// baseline (speedup 1.0000x reference)
#include <cuda_runtime.h>
#include <cuda_bf16.h>
#include <math.h>

// Problem constants
#define BATCH   2
#define NTOK    2048
#define DMODEL  1024
#define HEADS   16
#define DH      64
#define KOFF    8      // k = 8
#define DIL     2      // dilation = 2
#define NOFF    17     // 2*k + 1 valid offsets
#define EPSN    1e-6f

#define MROWS   (BATCH * NTOK)       // 4096
#define QKVCOLS (3 * DMODEL)         // 3072

// Scratch (device-global; no runtime allocation allowed)
__device__ float g_qkv[(size_t)MROWS * QKVCOLS];   // [4096, 3072]
__device__ float g_att[(size_t)MROWS * DMODEL];    // [4096, 1024]

// ---------------------------------------------------------------------------
// GEMM (NT): C[m,n] = sum_k A[m,k] * B[n,k] + bias[n]
// 128x128 tile, BK=8, 256 threads, 8x8 per-thread microtile.
// Shapes here are always multiples of the tile sizes (4096 x {3072,1024} x 1024).
// ---------------------------------------------------------------------------
#define BM 128
#define BN 128
#define BK 8

__global__ void __launch_bounds__(256) gemm_nt_bias(
    const float* __restrict__ A,    // [M, K]
    const float* __restrict__ B,    // [N, K]
    const float* __restrict__ bias, // [N]
    float* __restrict__ C,          // [M, N]
    int M, int N, int K)
{
    __shared__ float As[BK][BM];
    __shared__ float Bs[BK][BN];

    const int tid = threadIdx.x;
    const int m0  = blockIdx.y * BM;
    const int n0  = blockIdx.x * BN;

    // Global load mapping: 128 rows x 8 cols per tile; each thread one float4.
    const int lr = tid >> 1;         // 0..127 : row within tile
    const int lc = (tid & 1) * 4;    // 0 or 4 : col within BK

    // Compute mapping: 16x16 thread grid, 8x8 microtile each.
    const int ty = tid >> 4;         // 0..15
    const int tx = tid & 15;         // 0..15

    const float* Aptr = A + (size_t)(m0 + lr) * K + lc;
    const float* Bptr = B + (size_t)(n0 + lr) * K + lc;

    float acc[8][8];
    #pragma unroll
    for (int i = 0; i < 8; i++)
        #pragma unroll
        for (int j = 0; j < 8; j++)
            acc[i][j] = 0.0f;

    for (int k0 = 0; k0 < K; k0 += BK) {
        float4 a4 = *(const float4*)(Aptr + k0);
        float4 b4 = *(const float4*)(Bptr + k0);
        As[lc + 0][lr] = a4.x; As[lc + 1][lr] = a4.y;
        As[lc + 2][lr] = a4.z; As[lc + 3][lr] = a4.w;
        Bs[lc + 0][lr] = b4.x; Bs[lc + 1][lr] = b4.y;
        Bs[lc + 2][lr] = b4.z; Bs[lc + 3][lr] = b4.w;
        __syncthreads();

        #pragma unroll
        for (int k = 0; k < BK; k++) {
            float ar[8], br[8];
            #pragma unroll
            for (int i = 0; i < 8; i++) ar[i] = As[k][ty * 8 + i];
            #pragma unroll
            for (int j = 0; j < 8; j++) br[j] = Bs[k][tx * 8 + j];
            #pragma unroll
            for (int i = 0; i < 8; i++)
                #pragma unroll
                for (int j = 0; j < 8; j++)
                    acc[i][j] = fmaf(ar[i], br[j], acc[i][j]);
        }
        __syncthreads();
    }

    #pragma unroll
    for (int i = 0; i < 8; i++) {
        const int m = m0 + ty * 8 + i;
        #pragma unroll
        for (int j = 0; j < 8; j++) {
            const int n = n0 + tx * 8 + j;
            C[(size_t)m * N + n] = acc[i][j] + bias[n];
        }
    }
}

// ---------------------------------------------------------------------------
// QK-norm: one warp per (b, i, h); normalizes q row then k row in-place.
// row / (||row||_2 + eps)
// ---------------------------------------------------------------------------
__global__ void __launch_bounds__(128) qknorm_kernel(float* __restrict__ qkv)
{
    const int w    = blockIdx.x * 4 + (threadIdx.x >> 5);   // 0 .. B*N*H-1
    const int lane = threadIdx.x & 31;
    const int i = w & (NTOK - 1);
    const int h = (w >> 11) & (HEADS - 1);
    const int b = w >> 15;

    float* row = qkv + (size_t)(b * NTOK + i) * QKVCOLS + h * DH;

    #pragma unroll
    for (int part = 0; part < 2; part++) {          // 0 -> q, 1 -> k
        float2* p = (float2*)(row + part * DMODEL) + lane;
        float2 v = *p;
        float ss = v.x * v.x + v.y * v.y;
        ss += __shfl_xor_sync(0xffffffffu, ss, 16);
        ss += __shfl_xor_sync(0xffffffffu, ss, 8);
        ss += __shfl_xor_sync(0xffffffffu, ss, 4);
        ss += __shfl_xor_sync(0xffffffffu, ss, 2);
        ss += __shfl_xor_sync(0xffffffffu, ss, 1);
        const float sc = 1.0f / (sqrtf(ss) + EPSN);
        v.x *= sc; v.y *= sc;
        *p = v;
    }
}

// ---------------------------------------------------------------------------
// Dilated attention: one warp per (b, h, i). Only the 17 allowed offsets
// are touched. dh=64 -> float2 per lane. Scores reduced warp-wide so every
// lane holds all 17 scores; softmax in registers; weighted V accumulation.
// Output layout [b, n, h*64+d] == [B, N, D] so it feeds the out-proj GEMM.
// ---------------------------------------------------------------------------
__global__ void __launch_bounds__(128) attn_kernel(
    const float* __restrict__ qkv, float* __restrict__ att)
{
    const int w    = blockIdx.x * 4 + (threadIdx.x >> 5);   // 0 .. B*H*N-1
    const int lane = threadIdx.x & 31;
    const int i = w & (NTOK - 1);
    const int h = (w >> 11) & (HEADS - 1);
    const int b = w >> 15;

    const int d = lane * 2;
    const size_t rowstride = QKVCOLS;
    const float* qrow = qkv + (size_t)(b * NTOK + i) * rowstride + h * DH + d;
    const float2 q = *(const float2*)qrow;

    float s[NOFF];
    #pragma unroll
    for (int t = 0; t < NOFF; t++) {
        const int j = i + (t - KOFF) * DIL;
        if (j >= 0 && j < NTOK) {
            const float2 kv = *(const float2*)(
                qkv + (size_t)(b * NTOK + j) * rowstride + DMODEL + h * DH + d);
            float p = q.x * kv.x + q.y * kv.y;
            p += __shfl_xor_sync(0xffffffffu, p, 16);
            p += __shfl_xor_sync(0xffffffffu, p, 8);
            p += __shfl_xor_sync(0xffffffffu, p, 4);
            p += __shfl_xor_sync(0xffffffffu, p, 2);
            p += __shfl_xor_sync(0xffffffffu, p, 1);
            s[t] = p;
        } else {
            s[t] = -1e30f;
        }
    }

    float mx = s[0];
    #pragma unroll
    for (int t = 1; t < NOFF; t++) mx = fmaxf(mx, s[t]);

    float wgt[NOFF];
    float denom = 0.0f;
    #pragma unroll
    for (int t = 0; t < NOFF; t++) {
        wgt[t] = __expf(s[t] - mx);
        denom += wgt[t];
    }
    const float inv = 1.0f / denom;

    float2 acc = make_float2(0.0f, 0.0f);
    #pragma unroll
    for (int t = 0; t < NOFF; t++) {
        const int j = i + (t - KOFF) * DIL;
        if (j >= 0 && j < NTOK) {
            const float2 v = *(const float2*)(
                qkv + (size_t)(b * NTOK + j) * rowstride + 2 * DMODEL + h * DH + d);
            const float ww = wgt[t] * inv;
            acc.x = fmaf(ww, v.x, acc.x);
            acc.y = fmaf(ww, v.y, acc.y);
        }
    }

    *(float2*)(att + (size_t)(b * NTOK + i) * DMODEL + h * DH + d) = acc;
}

// ---------------------------------------------------------------------------
// Launch
// ---------------------------------------------------------------------------
extern "C" void kernel_launch(void* const* d_in, const int* in_sizes, int n_in,
                              void* d_out, int out_size)
{
    const float* x     = (const float*)d_in[0];
    const float* w_qkv = (const float*)d_in[1];
    const float* b_qkv = (const float*)d_in[2];
    const float* w_out = (const float*)d_in[3];
    const float* b_out = (const float*)d_in[4];
    float* out = (float*)d_out;

    float *qkv, *att;
    cudaGetSymbolAddress((void**)&qkv, g_qkv);
    cudaGetSymbolAddress((void**)&att, g_att);

    // 1) QKV projection: [4096,3072]
    {
        dim3 grid(QKVCOLS / BN, MROWS / BM);   // (24, 32)
        gemm_nt_bias<<<grid, 256>>>(x, w_qkv, b_qkv, qkv, MROWS, QKVCOLS, DMODEL);
    }
    // 2) QK norm (in place)
    qknorm_kernel<<<(BATCH * NTOK * HEADS) / 4, 128>>>(qkv);
    // 3) Dilated attention
    attn_kernel<<<(BATCH * HEADS * NTOK) / 4, 128>>>(qkv, att);
    // 4) Output projection: [4096,1024]
    {
        dim3 grid(DMODEL / BN, MROWS / BM);    // (8, 32)
        gemm_nt_bias<<<grid, 256>>>(att, w_out, b_out, out, MROWS, DMODEL, DMODEL);
    }
}

// round 3
// speedup vs baseline: 3.7806x; 3.7806x over previous
#include <cuda_runtime.h>
#include <cuda_fp16.h>
#include <math.h>
#include <stdint.h>

// ---------------------------------------------------------------------------
// Problem constants
// ---------------------------------------------------------------------------
#define BATCH   2
#define NTOK    2048
#define DMODEL  1024
#define HEADS   16
#define DH      64
#define KOFF    8
#define DIL     2
#define NOFF    17
#define EPSN    1e-6f
#define MROWS   (BATCH * NTOK)       // 4096
#define QKVCOLS (3 * DMODEL)         // 3072
#define GK      1024                 // inner dim of both GEMMs

// ---------------------------------------------------------------------------
// Scratch (device globals; no runtime allocation allowed)
// ---------------------------------------------------------------------------
__device__ __align__(256) float   g_qkv[(size_t)MROWS * QKVCOLS];
__device__ __align__(256) __half  g_xhi[(size_t)MROWS * DMODEL];
__device__ __align__(256) __half  g_xlo[(size_t)MROWS * DMODEL];
__device__ __align__(256) __half  g_wq16[(size_t)QKVCOLS * DMODEL];
__device__ __align__(256) __half  g_wo16[(size_t)DMODEL * DMODEL];
__device__ __align__(256) __half  g_atthi[(size_t)MROWS * DMODEL];
__device__ __align__(256) __half  g_attlo[(size_t)MROWS * DMODEL];

// ---------------------------------------------------------------------------
// Inline PTX helpers (all baseline sm_80+ ISA, nothing 'a'-gated)
// ---------------------------------------------------------------------------
__device__ __forceinline__ uint32_t s2u(const void* p) {
    uint32_t a;
    asm("{ .reg .u64 t; cvta.to.shared.u64 t, %1; cvt.u32.u64 %0, t; }"
        : "=r"(a) : "l"(p));
    return a;
}

__device__ __forceinline__ void cp16(uint32_t dst, const void* src) {
    asm volatile("cp.async.cg.shared.global [%0], [%1], 16;"
                 :: "r"(dst), "l"(src));
}
#define CP_COMMIT() asm volatile("cp.async.commit_group;")
#define CP_WAIT1()  asm volatile("cp.async.wait_group 1;")

__device__ __forceinline__ void ldsm4(uint32_t* r, uint32_t addr) {
    asm volatile("ldmatrix.sync.aligned.m8n8.x4.shared.b16 {%0,%1,%2,%3}, [%4];"
                 : "=r"(r[0]), "=r"(r[1]), "=r"(r[2]), "=r"(r[3]) : "r"(addr));
}

__device__ __forceinline__ void mma16816(float* c, const uint32_t* a,
                                         const uint32_t* b) {
    asm volatile(
        "mma.sync.aligned.m16n8k16.row.col.f32.f16.f16.f32 "
        "{%0,%1,%2,%3},{%4,%5,%6,%7},{%8,%9},{%0,%1,%2,%3};"
        : "+f"(c[0]), "+f"(c[1]), "+f"(c[2]), "+f"(c[3])
        : "r"(a[0]), "r"(a[1]), "r"(a[2]), "r"(a[3]), "r"(b[0]), "r"(b[1]));
}

#define SW128(x) ((x) ^ (((x) >> 3) & 0x70))

// ---------------------------------------------------------------------------
// HMMA GEMM (NT): C[m,n] = sum_k (Ahi[m,k]+Alo[m,k]) * B16[n,k] + bias[n]
// BM=BN=128, BK=64, 3-stage cp.async pipeline, 8 warps (64x32 warp tiles).
// ---------------------------------------------------------------------------
#define BM 128
#define BN 128
#define BK 64
#define STAGES 3
#define NITER (GK / BK)              // 16
#define TILE_B (128 * 128)           // 16 KB: 128 rows x 128 bytes
#define STAGE_B (3 * TILE_B)         // Ahi + Alo + B
#define GEMM_SMEM (STAGES * STAGE_B) // 147456

__device__ __forceinline__ void load_stage(
    uint32_t sb, int s, const __half* __restrict__ Ahi,
    const __half* __restrict__ Alo, const __half* __restrict__ Bw,
    int m0, int n0, int kc)
{
    const uint32_t base = sb + s * STAGE_B;
    #pragma unroll
    for (int u = threadIdx.x; u < 1024; u += 256) {
        const int r = u >> 3, ch = u & 7;
        const uint32_t sw = SW128((uint32_t)(r * 128 + ch * 16));
        const size_t offA = (size_t)(m0 + r) * GK + kc + ch * 8;
        const size_t offB = (size_t)(n0 + r) * GK + kc + ch * 8;
        cp16(base + sw,              Ahi + offA);
        cp16(base + TILE_B + sw,     Alo + offA);
        cp16(base + 2 * TILE_B + sw, Bw + offB);
    }
}

__global__ void __launch_bounds__(256, 1) gemm_hmma(
    const __half* __restrict__ Ahi, const __half* __restrict__ Alo,
    const __half* __restrict__ Bw,  const float* __restrict__ bias,
    float* __restrict__ C, int N)
{
    extern __shared__ char smem[];
    const uint32_t sb = s2u(smem);
    const int tid  = threadIdx.x;
    const int wid  = tid >> 5;
    const int lane = tid & 31;
    const int m0 = blockIdx.y * BM;
    const int n0 = blockIdx.x * BN;
    const int warp_m = (wid & 1) * 64;
    const int warp_n = (wid >> 1) * 32;

    // ldmatrix lane geometry
    const int aRow = lane & 15;           // m offset within m16 tile
    const int aKc  = (lane >> 4) & 1;     // 16B chunk within k16
    const int bRow = ((lane >> 4) << 3) + (lane & 7);  // n offset within n16
    const int bK   = (lane >> 3) & 1;     // 16B chunk within k16

    float acc[4][4][4];
    #pragma unroll
    for (int i = 0; i < 4; i++)
        #pragma unroll
        for (int j = 0; j < 4; j++)
            #pragma unroll
            for (int q = 0; q < 4; q++) acc[i][j][q] = 0.0f;

    load_stage(sb, 0, Ahi, Alo, Bw, m0, n0, 0);
    CP_COMMIT();
    load_stage(sb, 1, Ahi, Alo, Bw, m0, n0, BK);
    CP_COMMIT();

    for (int it = 0; it < NITER; it++) {
        CP_WAIT1();
        __syncthreads();
        if (it + 2 < NITER)
            load_stage(sb, (it + 2) % STAGES, Ahi, Alo, Bw, m0, n0, (it + 2) * BK);
        CP_COMMIT();

        const uint32_t Ab = sb + (it % STAGES) * STAGE_B;
        const uint32_t Lb = Ab + TILE_B;
        const uint32_t Bb = Ab + 2 * TILE_B;

        #pragma unroll
        for (int ks = 0; ks < 4; ks++) {
            uint32_t bfr[2][4];
            #pragma unroll
            for (int nt2 = 0; nt2 < 2; nt2++) {
                const uint32_t off = (uint32_t)((warp_n + nt2 * 16 + bRow) * 128
                                                + ks * 32 + bK * 16);
                ldsm4(bfr[nt2], Bb + SW128(off));
            }
            uint32_t ah[4][4];
            #pragma unroll
            for (int mt = 0; mt < 4; mt++) {
                const uint32_t off = (uint32_t)((warp_m + mt * 16 + aRow) * 128
                                                + ks * 32 + aKc * 16);
                ldsm4(ah[mt], Ab + SW128(off));
            }
            #pragma unroll
            for (int mt = 0; mt < 4; mt++)
                #pragma unroll
                for (int nt = 0; nt < 4; nt++)
                    mma16816(acc[mt][nt], ah[mt], &bfr[nt >> 1][(nt & 1) * 2]);
            uint32_t al[4][4];
            #pragma unroll
            for (int mt = 0; mt < 4; mt++) {
                const uint32_t off = (uint32_t)((warp_m + mt * 16 + aRow) * 128
                                                + ks * 32 + aKc * 16);
                ldsm4(al[mt], Lb + SW128(off));
            }
            #pragma unroll
            for (int mt = 0; mt < 4; mt++)
                #pragma unroll
                for (int nt = 0; nt < 4; nt++)
                    mma16816(acc[mt][nt], al[mt], &bfr[nt >> 1][(nt & 1) * 2]);
        }
    }

    // Epilogue: fused bias, float2 stores
    const int lr = lane >> 2;             // 0..7
    const int lc = (lane & 3) * 2;        // 0,2,4,6
    #pragma unroll
    for (int mt = 0; mt < 4; mt++) {
        #pragma unroll
        for (int nt = 0; nt < 4; nt++) {
            const int col = n0 + warp_n + nt * 8 + lc;
            const float2 bi = *(const float2*)(bias + col);
            const int row0 = m0 + warp_m + mt * 16 + lr;
            float2 v0 = make_float2(acc[mt][nt][0] + bi.x, acc[mt][nt][1] + bi.y);
            float2 v1 = make_float2(acc[mt][nt][2] + bi.x, acc[mt][nt][3] + bi.y);
            *(float2*)(C + (size_t)row0 * N + col) = v0;
            *(float2*)(C + (size_t)(row0 + 8) * N + col) = v1;
        }
    }
}

// ---------------------------------------------------------------------------
// fp32 -> (hi, lo) fp16 split (exact 22-bit capture)
// ---------------------------------------------------------------------------
__global__ void __launch_bounds__(256) split_kernel(
    const float* __restrict__ s, __half* __restrict__ hi,
    __half* __restrict__ lo, int n)
{
    int i = (blockIdx.x * 256 + threadIdx.x) * 4;
    if (i >= n) return;
    float4 v = *(const float4*)(s + i);
    __half h0 = __float2half_rn(v.x), h1 = __float2half_rn(v.y);
    __half h2 = __float2half_rn(v.z), h3 = __float2half_rn(v.w);
    __half l0 = __float2half_rn(v.x - __half2float(h0));
    __half l1 = __float2half_rn(v.y - __half2float(h1));
    __half l2 = __float2half_rn(v.z - __half2float(h2));
    __half l3 = __float2half_rn(v.w - __half2float(h3));
    union { __half h[4]; uint2 u; } H = {{h0, h1, h2, h3}}, L = {{l0, l1, l2, l3}};
    *(uint2*)(hi + i) = H.u;
    *(uint2*)(lo + i) = L.u;
}

// fp32 -> fp16 round (weights)
__global__ void __launch_bounds__(256) round_kernel(
    const float* __restrict__ s, __half* __restrict__ d, int n)
{
    int i = (blockIdx.x * 256 + threadIdx.x) * 4;
    if (i >= n) return;
    float4 v = *(const float4*)(s + i);
    union { __half h[4]; uint2 u; } H = {{__float2half_rn(v.x), __float2half_rn(v.y),
                                          __float2half_rn(v.z), __float2half_rn(v.w)}};
    *(uint2*)(d + i) = H.u;
}

// ---------------------------------------------------------------------------
// QK-norm: one warp per (b, i, h); normalizes q and k rows in-place.
// ---------------------------------------------------------------------------
__global__ void __launch_bounds__(128) qknorm_kernel(float* __restrict__ qkv)
{
    const int w    = blockIdx.x * 4 + (threadIdx.x >> 5);
    const int lane = threadIdx.x & 31;
    const int i = w & (NTOK - 1);
    const int h = (w >> 11) & (HEADS - 1);
    const int b = w >> 15;

    float* row = qkv + (size_t)(b * NTOK + i) * QKVCOLS + h * DH;

    #pragma unroll
    for (int part = 0; part < 2; part++) {
        float2* p = (float2*)(row + part * DMODEL) + lane;
        float2 v = *p;
        float ss = v.x * v.x + v.y * v.y;
        ss += __shfl_xor_sync(0xffffffffu, ss, 16);
        ss += __shfl_xor_sync(0xffffffffu, ss, 8);
        ss += __shfl_xor_sync(0xffffffffu, ss, 4);
        ss += __shfl_xor_sync(0xffffffffu, ss, 2);
        ss += __shfl_xor_sync(0xffffffffu, ss, 1);
        const float sc = 1.0f / (sqrtf(ss) + EPSN);
        v.x *= sc; v.y *= sc;
        *p = v;
    }
}

// ---------------------------------------------------------------------------
// Dilated attention: one warp per (b, h, i); 17 allowed offsets only.
// Output written directly as (hi, lo) fp16 split for the out-proj GEMM.
// ---------------------------------------------------------------------------
__global__ void __launch_bounds__(128) attn_kernel(
    const float* __restrict__ qkv, __half* __restrict__ ahi,
    __half* __restrict__ alo)
{
    const int w    = blockIdx.x * 4 + (threadIdx.x >> 5);
    const int lane = threadIdx.x & 31;
    const int i = w & (NTOK - 1);
    const int h = (w >> 11) & (HEADS - 1);
    const int b = w >> 15;

    const int d = lane * 2;
    const float2 q = *(const float2*)(
        qkv + (size_t)(b * NTOK + i) * QKVCOLS + h * DH + d);

    float s[NOFF];
    #pragma unroll
    for (int t = 0; t < NOFF; t++) {
        const int j = i + (t - KOFF) * DIL;
        if (j >= 0 && j < NTOK) {
            const float2 kv = *(const float2*)(
                qkv + (size_t)(b * NTOK + j) * QKVCOLS + DMODEL + h * DH + d);
            float p = q.x * kv.x + q.y * kv.y;
            p += __shfl_xor_sync(0xffffffffu, p, 16);
            p += __shfl_xor_sync(0xffffffffu, p, 8);
            p += __shfl_xor_sync(0xffffffffu, p, 4);
            p += __shfl_xor_sync(0xffffffffu, p, 2);
            p += __shfl_xor_sync(0xffffffffu, p, 1);
            s[t] = p;
        } else {
            s[t] = -1e30f;
        }
    }

    float mx = s[0];
    #pragma unroll
    for (int t = 1; t < NOFF; t++) mx = fmaxf(mx, s[t]);

    float wgt[NOFF];
    float denom = 0.0f;
    #pragma unroll
    for (int t = 0; t < NOFF; t++) { wgt[t] = __expf(s[t] - mx); denom += wgt[t]; }
    const float inv = 1.0f / denom;

    float2 acc = make_float2(0.0f, 0.0f);
    #pragma unroll
    for (int t = 0; t < NOFF; t++) {
        const int j = i + (t - KOFF) * DIL;
        if (j >= 0 && j < NTOK) {
            const float2 v = *(const float2*)(
                qkv + (size_t)(b * NTOK + j) * QKVCOLS + 2 * DMODEL + h * DH + d);
            const float ww = wgt[t] * inv;
            acc.x = fmaf(ww, v.x, acc.x);
            acc.y = fmaf(ww, v.y, acc.y);
        }
    }

    const size_t o = (size_t)(b * NTOK + i) * DMODEL + h * DH + d;
    __half hx = __float2half_rn(acc.x), hy = __float2half_rn(acc.y);
    __half lx = __float2half_rn(acc.x - __half2float(hx));
    __half ly = __float2half_rn(acc.y - __half2float(hy));
    *(__half2*)(ahi + o) = __halves2half2(hx, hy);
    *(__half2*)(alo + o) = __halves2half2(lx, ly);
}

// ---------------------------------------------------------------------------
// Launch
// ---------------------------------------------------------------------------
extern "C" void kernel_launch(void* const* d_in, const int* in_sizes, int n_in,
                              void* d_out, int out_size)
{
    const float* x     = (const float*)d_in[0];
    const float* w_qkv = (const float*)d_in[1];
    const float* b_qkv = (const float*)d_in[2];
    const float* w_out = (const float*)d_in[3];
    const float* b_out = (const float*)d_in[4];
    float* out = (float*)d_out;

    float* qkv;
    __half *xhi, *xlo, *wq16, *wo16, *ahi, *alo;
    cudaGetSymbolAddress((void**)&qkv,  g_qkv);
    cudaGetSymbolAddress((void**)&xhi,  g_xhi);
    cudaGetSymbolAddress((void**)&xlo,  g_xlo);
    cudaGetSymbolAddress((void**)&wq16, g_wq16);
    cudaGetSymbolAddress((void**)&wo16, g_wo16);
    cudaGetSymbolAddress((void**)&ahi,  g_atthi);
    cudaGetSymbolAddress((void**)&alo,  g_attlo);

    cudaFuncSetAttribute(gemm_hmma, cudaFuncAttributeMaxDynamicSharedMemorySize,
                         GEMM_SMEM);

    // Preprocessing: splits / rounds
    split_kernel<<<(MROWS * DMODEL) / 1024, 256>>>(x, xhi, xlo, MROWS * DMODEL);
    round_kernel<<<(QKVCOLS * DMODEL) / 1024, 256>>>(w_qkv, wq16, QKVCOLS * DMODEL);
    round_kernel<<<(DMODEL * DMODEL) / 1024, 256>>>(w_out, wo16, DMODEL * DMODEL);

    // 1) QKV projection: [4096, 3072]
    {
        dim3 grid(QKVCOLS / BN, MROWS / BM);   // (24, 32)
        gemm_hmma<<<grid, 256, GEMM_SMEM>>>(xhi, xlo, wq16, b_qkv, qkv, QKVCOLS);
    }
    // 2) QK norm (in place)
    qknorm_kernel<<<(BATCH * NTOK * HEADS) / 4, 128>>>(qkv);
    // 3) Dilated attention (writes fp16 hi/lo directly)
    attn_kernel<<<(BATCH * HEADS * NTOK) / 4, 128>>>(qkv, ahi, alo);
    // 4) Output projection: [4096, 1024]
    {
        dim3 grid(DMODEL / BN, MROWS / BM);    // (8, 32)
        gemm_hmma<<<grid, 256, GEMM_SMEM>>>(ahi, alo, wo16, b_out, out, DMODEL);
    }
}

// round 4
// speedup vs baseline: 4.2475x; 1.1235x over previous
#include <cuda_runtime.h>
#include <cuda_fp16.h>
#include <math.h>
#include <stdint.h>

// ---------------------------------------------------------------------------
// Problem constants
// ---------------------------------------------------------------------------
#define BATCH   2
#define NTOK    2048
#define DMODEL  1024
#define HEADS   16
#define DH      64
#define KOFF    8
#define DIL     2
#define NOFF    17
#define EPSN    1e-6f
#define MROWS   (BATCH * NTOK)       // 4096
#define QKVCOLS (3 * DMODEL)         // 3072
#define GK      1024                 // inner dim of both GEMMs

// ---------------------------------------------------------------------------
// Scratch (device globals; no runtime allocation allowed)
// ---------------------------------------------------------------------------
__device__ __align__(256) float   g_qkv[(size_t)MROWS * QKVCOLS];
__device__ __align__(256) __half  g_x16[(size_t)MROWS * DMODEL];
__device__ __align__(256) __half  g_wq16[(size_t)QKVCOLS * DMODEL];
__device__ __align__(256) __half  g_wo16[(size_t)DMODEL * DMODEL];
__device__ __align__(256) __half  g_att16[(size_t)MROWS * DMODEL];

// ---------------------------------------------------------------------------
// Inline PTX helpers (baseline sm_80+ ISA only)
// ---------------------------------------------------------------------------
__device__ __forceinline__ uint32_t s2u(const void* p) {
    uint32_t a;
    asm("{ .reg .u64 t; cvta.to.shared.u64 t, %1; cvt.u32.u64 %0, t; }"
        : "=r"(a) : "l"(p));
    return a;
}

__device__ __forceinline__ void cp16(uint32_t dst, const void* src) {
    asm volatile("cp.async.cg.shared.global [%0], [%1], 16;"
                 :: "r"(dst), "l"(src));
}
#define CP_COMMIT() asm volatile("cp.async.commit_group;")
#define CP_WAIT2()  asm volatile("cp.async.wait_group 2;")

__device__ __forceinline__ void ldsm4(uint32_t* r, uint32_t addr) {
    asm volatile("ldmatrix.sync.aligned.m8n8.x4.shared.b16 {%0,%1,%2,%3}, [%4];"
                 : "=r"(r[0]), "=r"(r[1]), "=r"(r[2]), "=r"(r[3]) : "r"(addr));
}

__device__ __forceinline__ void mma16816(float* c, const uint32_t* a,
                                         const uint32_t* b) {
    asm volatile(
        "mma.sync.aligned.m16n8k16.row.col.f32.f16.f16.f32 "
        "{%0,%1,%2,%3},{%4,%5,%6,%7},{%8,%9},{%0,%1,%2,%3};"
        : "+f"(c[0]), "+f"(c[1]), "+f"(c[2]), "+f"(c[3])
        : "r"(a[0]), "r"(a[1]), "r"(a[2]), "r"(a[3]), "r"(b[0]), "r"(b[1]));
}

#define SW128(x) ((x) ^ (((x) >> 3) & 0x70))

// ---------------------------------------------------------------------------
// Single-pass fp16 HMMA GEMM (NT): C[m,n] = sum_k A[m,k]*B[n,k] + bias[n]
// BM=BN=128, BK=64; 512 threads, 16 warps (32x32 warp tiles);
// 4-stage cp.async pipeline (prefetch depth 3), 128 KB SMEM.
// ---------------------------------------------------------------------------
#define BM 128
#define BN 128
#define BK 64
#define STAGES 4
#define NITER (GK / BK)              // 16
#define TILE_B (128 * 128)           // 16 KB: 128 rows x 128 bytes
#define STAGE_B (2 * TILE_B)         // A + B
#define GEMM_SMEM (STAGES * STAGE_B) // 131072

__device__ __forceinline__ void load_stage(
    uint32_t sb, int s, const __half* __restrict__ A,
    const __half* __restrict__ Bw, int m0, int n0, int kc)
{
    const uint32_t base = sb + s * STAGE_B;
    #pragma unroll
    for (int u = threadIdx.x; u < 1024; u += 512) {
        const int r = u >> 3, ch = u & 7;
        const uint32_t sw = SW128((uint32_t)(r * 128 + ch * 16));
        cp16(base + sw,          A  + (size_t)(m0 + r) * GK + kc + ch * 8);
        cp16(base + TILE_B + sw, Bw + (size_t)(n0 + r) * GK + kc + ch * 8);
    }
}

__global__ void __launch_bounds__(512, 1) gemm_hmma(
    const __half* __restrict__ A, const __half* __restrict__ Bw,
    const float* __restrict__ bias, float* __restrict__ C, int N)
{
    extern __shared__ char smem[];
    const uint32_t sb = s2u(smem);
    const int tid  = threadIdx.x;
    const int wid  = tid >> 5;
    const int lane = tid & 31;
    const int m0 = blockIdx.y * BM;
    const int n0 = blockIdx.x * BN;
    const int warp_m = (wid & 3) * 32;
    const int warp_n = (wid >> 2) * 32;

    // ldmatrix lane geometry (validated in R3)
    const int aRow = lane & 15;
    const int aKc  = (lane >> 4) & 1;
    const int bRow = ((lane >> 4) << 3) + (lane & 7);
    const int bK   = (lane >> 3) & 1;

    float acc[2][4][4];
    #pragma unroll
    for (int i = 0; i < 2; i++)
        #pragma unroll
        for (int j = 0; j < 4; j++)
            #pragma unroll
            for (int q = 0; q < 4; q++) acc[i][j][q] = 0.0f;

    load_stage(sb, 0, A, Bw, m0, n0, 0);       CP_COMMIT();
    load_stage(sb, 1, A, Bw, m0, n0, BK);      CP_COMMIT();
    load_stage(sb, 2, A, Bw, m0, n0, 2 * BK);  CP_COMMIT();

    for (int it = 0; it < NITER; it++) {
        CP_WAIT2();
        __syncthreads();
        if (it + 3 < NITER)
            load_stage(sb, (it + 3) & 3, A, Bw, m0, n0, (it + 3) * BK);
        CP_COMMIT();

        const uint32_t Ab = sb + (it & 3) * STAGE_B;
        const uint32_t Bb = Ab + TILE_B;

        #pragma unroll
        for (int ks = 0; ks < 4; ks++) {
            uint32_t bfr[2][4];
            #pragma unroll
            for (int nt2 = 0; nt2 < 2; nt2++) {
                const uint32_t off = (uint32_t)((warp_n + nt2 * 16 + bRow) * 128
                                                + ks * 32 + bK * 16);
                ldsm4(bfr[nt2], Bb + SW128(off));
            }
            uint32_t ah[2][4];
            #pragma unroll
            for (int mt = 0; mt < 2; mt++) {
                const uint32_t off = (uint32_t)((warp_m + mt * 16 + aRow) * 128
                                                + ks * 32 + aKc * 16);
                ldsm4(ah[mt], Ab + SW128(off));
            }
            #pragma unroll
            for (int mt = 0; mt < 2; mt++)
                #pragma unroll
                for (int nt = 0; nt < 4; nt++)
                    mma16816(acc[mt][nt], ah[mt], &bfr[nt >> 1][(nt & 1) * 2]);
        }
    }

    // Epilogue: fused bias, float2 stores
    const int lr = lane >> 2;
    const int lc = (lane & 3) * 2;
    #pragma unroll
    for (int mt = 0; mt < 2; mt++) {
        #pragma unroll
        for (int nt = 0; nt < 4; nt++) {
            const int col = n0 + warp_n + nt * 8 + lc;
            const float2 bi = *(const float2*)(bias + col);
            const int row0 = m0 + warp_m + mt * 16 + lr;
            float2 v0 = make_float2(acc[mt][nt][0] + bi.x, acc[mt][nt][1] + bi.y);
            float2 v1 = make_float2(acc[mt][nt][2] + bi.x, acc[mt][nt][3] + bi.y);
            *(float2*)(C + (size_t)row0 * N + col) = v0;
            *(float2*)(C + (size_t)(row0 + 8) * N + col) = v1;
        }
    }
}

// ---------------------------------------------------------------------------
// fp32 -> fp16 round
// ---------------------------------------------------------------------------
__global__ void __launch_bounds__(256) round_kernel(
    const float* __restrict__ s, __half* __restrict__ d, int n)
{
    int i = (blockIdx.x * 256 + threadIdx.x) * 4;
    if (i >= n) return;
    float4 v = *(const float4*)(s + i);
    union { __half h[4]; uint2 u; } H = {{__float2half_rn(v.x), __float2half_rn(v.y),
                                          __float2half_rn(v.z), __float2half_rn(v.w)}};
    *(uint2*)(d + i) = H.u;
}

// ---------------------------------------------------------------------------
// Fused QK-norm + dilated attention: one warp per (b, h, i).
// score = dot(q_i, k_j) / ((|q_i|+eps)(|k_j|+eps)); 17 allowed offsets.
// Output rounded to fp16 directly for the out-proj GEMM.
// ---------------------------------------------------------------------------
__global__ void __launch_bounds__(128) attn_kernel(
    const float* __restrict__ qkv, __half* __restrict__ att)
{
    const int w    = blockIdx.x * 4 + (threadIdx.x >> 5);
    const int lane = threadIdx.x & 31;
    const int i = w & (NTOK - 1);
    const int h = (w >> 11) & (HEADS - 1);
    const int b = w >> 15;

    const int d = lane * 2;
    const float2 q = *(const float2*)(
        qkv + (size_t)(b * NTOK + i) * QKVCOLS + h * DH + d);

    // |q|
    float qq = q.x * q.x + q.y * q.y;
    qq += __shfl_xor_sync(0xffffffffu, qq, 16);
    qq += __shfl_xor_sync(0xffffffffu, qq, 8);
    qq += __shfl_xor_sync(0xffffffffu, qq, 4);
    qq += __shfl_xor_sync(0xffffffffu, qq, 2);
    qq += __shfl_xor_sync(0xffffffffu, qq, 1);
    const float qinv = 1.0f / (sqrtf(qq) + EPSN);

    float s[NOFF];
    #pragma unroll
    for (int t = 0; t < NOFF; t++) {
        const int j = i + (t - KOFF) * DIL;
        if (j >= 0 && j < NTOK) {
            const float2 kv = *(const float2*)(
                qkv + (size_t)(b * NTOK + j) * QKVCOLS + DMODEL + h * DH + d);
            float p  = q.x * kv.x + q.y * kv.y;
            float kk = kv.x * kv.x + kv.y * kv.y;
            #pragma unroll
            for (int m = 16; m >= 1; m >>= 1) {
                p  += __shfl_xor_sync(0xffffffffu, p,  m);
                kk += __shfl_xor_sync(0xffffffffu, kk, m);
            }
            s[t] = p * qinv / (sqrtf(kk) + EPSN);
        } else {
            s[t] = -1e30f;
        }
    }

    float mx = s[0];
    #pragma unroll
    for (int t = 1; t < NOFF; t++) mx = fmaxf(mx, s[t]);

    float wgt[NOFF];
    float denom = 0.0f;
    #pragma unroll
    for (int t = 0; t < NOFF; t++) { wgt[t] = __expf(s[t] - mx); denom += wgt[t]; }
    const float inv = 1.0f / denom;

    float2 acc = make_float2(0.0f, 0.0f);
    #pragma unroll
    for (int t = 0; t < NOFF; t++) {
        const int j = i + (t - KOFF) * DIL;
        if (j >= 0 && j < NTOK) {
            const float2 v = *(const float2*)(
                qkv + (size_t)(b * NTOK + j) * QKVCOLS + 2 * DMODEL + h * DH + d);
            const float ww = wgt[t] * inv;
            acc.x = fmaf(ww, v.x, acc.x);
            acc.y = fmaf(ww, v.y, acc.y);
        }
    }

    const size_t o = (size_t)(b * NTOK + i) * DMODEL + h * DH + d;
    *(__half2*)(att + o) = __halves2half2(__float2half_rn(acc.x),
                                          __float2half_rn(acc.y));
}

// ---------------------------------------------------------------------------
// Launch
// ---------------------------------------------------------------------------
extern "C" void kernel_launch(void* const* d_in, const int* in_sizes, int n_in,
                              void* d_out, int out_size)
{
    const float* x     = (const float*)d_in[0];
    const float* w_qkv = (const float*)d_in[1];
    const float* b_qkv = (const float*)d_in[2];
    const float* w_out = (const float*)d_in[3];
    const float* b_out = (const float*)d_in[4];
    float* out = (float*)d_out;

    float* qkv;
    __half *x16, *wq16, *wo16, *att16;
    cudaGetSymbolAddress((void**)&qkv,   g_qkv);
    cudaGetSymbolAddress((void**)&x16,   g_x16);
    cudaGetSymbolAddress((void**)&wq16,  g_wq16);
    cudaGetSymbolAddress((void**)&wo16,  g_wo16);
    cudaGetSymbolAddress((void**)&att16, g_att16);

    cudaFuncSetAttribute(gemm_hmma, cudaFuncAttributeMaxDynamicSharedMemorySize,
                         GEMM_SMEM);

    // fp32 -> fp16 rounds
    round_kernel<<<(MROWS * DMODEL) / 1024, 256>>>(x, x16, MROWS * DMODEL);
    round_kernel<<<(QKVCOLS * DMODEL) / 1024, 256>>>(w_qkv, wq16, QKVCOLS * DMODEL);
    round_kernel<<<(DMODEL * DMODEL) / 1024, 256>>>(w_out, wo16, DMODEL * DMODEL);

    // 1) QKV projection: [4096, 3072]
    {
        dim3 grid(QKVCOLS / BN, MROWS / BM);   // (24, 32)
        gemm_hmma<<<grid, 512, GEMM_SMEM>>>(x16, wq16, b_qkv, qkv, QKVCOLS);
    }
    // 2) Fused QK-norm + dilated attention (writes fp16)
    attn_kernel<<<(BATCH * HEADS * NTOK) / 4, 128>>>(qkv, att16);
    // 3) Output projection: [4096, 1024]
    {
        dim3 grid(DMODEL / BN, MROWS / BM);    // (8, 32)
        gemm_hmma<<<grid, 512, GEMM_SMEM>>>(att16, wo16, b_out, out, DMODEL);
    }
}

// round 5
// speedup vs baseline: 5.2169x; 1.2282x over previous
#include <cuda_runtime.h>
#include <cuda_fp16.h>
#include <math.h>
#include <stdint.h>

// ---------------------------------------------------------------------------
// Problem constants
// ---------------------------------------------------------------------------
#define BATCH   2
#define NTOK    2048
#define DMODEL  1024
#define HEADS   16
#define DH      64
#define KOFF    8
#define DIL     2
#define NOFF    17
#define EPSN    1e-6f
#define MROWS   (BATCH * NTOK)       // 4096
#define QKVCOLS (3 * DMODEL)         // 3072
#define GK      1024                 // inner dim of both GEMMs

// ---------------------------------------------------------------------------
// Scratch (device globals; no runtime allocation allowed)
// ---------------------------------------------------------------------------
__device__ __align__(256) float   g_qkv[(size_t)MROWS * QKVCOLS];
__device__ __align__(256) __half  g_x16[(size_t)MROWS * DMODEL];
__device__ __align__(256) __half  g_wq16[(size_t)QKVCOLS * DMODEL];
__device__ __align__(256) __half  g_wo16[(size_t)DMODEL * DMODEL];
__device__ __align__(256) __half  g_att16[(size_t)MROWS * DMODEL];

// ---------------------------------------------------------------------------
// Inline PTX helpers (baseline sm_80+ ISA only)
// ---------------------------------------------------------------------------
__device__ __forceinline__ uint32_t s2u(const void* p) {
    uint32_t a;
    asm("{ .reg .u64 t; cvta.to.shared.u64 t, %1; cvt.u32.u64 %0, t; }"
        : "=r"(a) : "l"(p));
    return a;
}

__device__ __forceinline__ void cp16(uint32_t dst, const void* src) {
    asm volatile("cp.async.cg.shared.global [%0], [%1], 16;"
                 :: "r"(dst), "l"(src));
}
#define CP_COMMIT() asm volatile("cp.async.commit_group;")
#define CP_WAIT2()  asm volatile("cp.async.wait_group 2;")

__device__ __forceinline__ void ldsm4(uint32_t* r, uint32_t addr) {
    asm volatile("ldmatrix.sync.aligned.m8n8.x4.shared.b16 {%0,%1,%2,%3}, [%4];"
                 : "=r"(r[0]), "=r"(r[1]), "=r"(r[2]), "=r"(r[3]) : "r"(addr));
}

__device__ __forceinline__ void mma16816(float* c, const uint32_t* a,
                                         const uint32_t* b) {
    asm volatile(
        "mma.sync.aligned.m16n8k16.row.col.f32.f16.f16.f32 "
        "{%0,%1,%2,%3},{%4,%5,%6,%7},{%8,%9},{%0,%1,%2,%3};"
        : "+f"(c[0]), "+f"(c[1]), "+f"(c[2]), "+f"(c[3])
        : "r"(a[0]), "r"(a[1]), "r"(a[2]), "r"(a[3]), "r"(b[0]), "r"(b[1]));
}

#define SW128(x) ((x) ^ (((x) >> 3) & 0x70))

// ---------------------------------------------------------------------------
// Single-pass fp16 HMMA GEMM (NT): C[m,n] = sum_k A[m,k]*B[n,k] + bias[n]
// BM=BN=128, BK=64; 256 threads, 8 warps (64x32 warp tiles, high ILP);
// 4-stage cp.async pipeline (prefetch depth 3), 128 KB SMEM.
// ---------------------------------------------------------------------------
#define BM 128
#define BN 128
#define BK 64
#define STAGES 4
#define NITER (GK / BK)              // 16
#define TILE_B (128 * 128)           // 16 KB: 128 rows x 128 bytes
#define STAGE_B (2 * TILE_B)         // A + B
#define GEMM_SMEM (STAGES * STAGE_B) // 131072

__device__ __forceinline__ void load_stage(
    uint32_t sb, int s, const __half* __restrict__ A,
    const __half* __restrict__ Bw, int m0, int n0, int kc)
{
    const uint32_t base = sb + s * STAGE_B;
    #pragma unroll
    for (int u = threadIdx.x; u < 1024; u += 256) {
        const int r = u >> 3, ch = u & 7;
        const uint32_t sw = SW128((uint32_t)(r * 128 + ch * 16));
        cp16(base + sw,          A  + (size_t)(m0 + r) * GK + kc + ch * 8);
        cp16(base + TILE_B + sw, Bw + (size_t)(n0 + r) * GK + kc + ch * 8);
    }
}

__global__ void __launch_bounds__(256, 1) gemm_hmma(
    const __half* __restrict__ A, const __half* __restrict__ Bw,
    const float* __restrict__ bias, float* __restrict__ C, int N)
{
    extern __shared__ char smem[];
    const uint32_t sb = s2u(smem);
    const int tid  = threadIdx.x;
    const int wid  = tid >> 5;
    const int lane = tid & 31;
    const int m0 = blockIdx.y * BM;
    const int n0 = blockIdx.x * BN;
    const int warp_m = (wid & 1) * 64;
    const int warp_n = (wid >> 1) * 32;

    // ldmatrix lane geometry (validated R3/R4)
    const int aRow = lane & 15;
    const int aKc  = (lane >> 4) & 1;
    const int bRow = ((lane >> 4) << 3) + (lane & 7);
    const int bK   = (lane >> 3) & 1;

    float acc[4][4][4];
    #pragma unroll
    for (int i = 0; i < 4; i++)
        #pragma unroll
        for (int j = 0; j < 4; j++)
            #pragma unroll
            for (int q = 0; q < 4; q++) acc[i][j][q] = 0.0f;

    load_stage(sb, 0, A, Bw, m0, n0, 0);       CP_COMMIT();
    load_stage(sb, 1, A, Bw, m0, n0, BK);      CP_COMMIT();
    load_stage(sb, 2, A, Bw, m0, n0, 2 * BK);  CP_COMMIT();

    for (int it = 0; it < NITER; it++) {
        CP_WAIT2();
        __syncthreads();
        if (it + 3 < NITER)
            load_stage(sb, (it + 3) & 3, A, Bw, m0, n0, (it + 3) * BK);
        CP_COMMIT();

        const uint32_t Ab = sb + (it & 3) * STAGE_B;
        const uint32_t Bb = Ab + TILE_B;

        #pragma unroll
        for (int ks = 0; ks < 4; ks++) {
            uint32_t bfr[2][4];
            #pragma unroll
            for (int nt2 = 0; nt2 < 2; nt2++) {
                const uint32_t off = (uint32_t)((warp_n + nt2 * 16 + bRow) * 128
                                                + ks * 32 + bK * 16);
                ldsm4(bfr[nt2], Bb + SW128(off));
            }
            uint32_t ah[4][4];
            #pragma unroll
            for (int mt = 0; mt < 4; mt++) {
                const uint32_t off = (uint32_t)((warp_m + mt * 16 + aRow) * 128
                                                + ks * 32 + aKc * 16);
                ldsm4(ah[mt], Ab + SW128(off));
            }
            #pragma unroll
            for (int mt = 0; mt < 4; mt++)
                #pragma unroll
                for (int nt = 0; nt < 4; nt++)
                    mma16816(acc[mt][nt], ah[mt], &bfr[nt >> 1][(nt & 1) * 2]);
        }
    }

    // Epilogue: fused bias, float2 stores
    const int lr = lane >> 2;
    const int lc = (lane & 3) * 2;
    #pragma unroll
    for (int mt = 0; mt < 4; mt++) {
        #pragma unroll
        for (int nt = 0; nt < 4; nt++) {
            const int col = n0 + warp_n + nt * 8 + lc;
            const float2 bi = *(const float2*)(bias + col);
            const int row0 = m0 + warp_m + mt * 16 + lr;
            float2 v0 = make_float2(acc[mt][nt][0] + bi.x, acc[mt][nt][1] + bi.y);
            float2 v1 = make_float2(acc[mt][nt][2] + bi.x, acc[mt][nt][3] + bi.y);
            *(float2*)(C + (size_t)row0 * N + col) = v0;
            *(float2*)(C + (size_t)(row0 + 8) * N + col) = v1;
        }
    }
}

// ---------------------------------------------------------------------------
// fp32 -> fp16 round
// ---------------------------------------------------------------------------
__global__ void __launch_bounds__(256) round_kernel(
    const float* __restrict__ s, __half* __restrict__ d, int n)
{
    int i = (blockIdx.x * 256 + threadIdx.x) * 4;
    if (i >= n) return;
    float4 v = *(const float4*)(s + i);
    union { __half h[4]; uint2 u; } H = {{__float2half_rn(v.x), __float2half_rn(v.y),
                                          __float2half_rn(v.z), __float2half_rn(v.w)}};
    *(uint2*)(d + i) = H.u;
}

// ---------------------------------------------------------------------------
// Fused QK-norm + dilated attention, SMEM-tiled.
// Block = 64 consecutive queries for one (b, h). The k/v window
// [i0-16, i0+79] (96 rows x 64 floats) is staged in SMEM; per-row k-norms
// are computed once. 8 warps x 8 queries each. Output rounded to fp16.
// ---------------------------------------------------------------------------
#define TI   64                       // queries per block
#define WND  (TI + 2 * KOFF * DIL)    // 96 window rows
#define ATT_SMEM ((2 * WND * DH + WND) * 4)   // ks + vs + kinv = 49536 B

__global__ void __launch_bounds__(256, 1) attn_kernel(
    const float* __restrict__ qkv, __half* __restrict__ att)
{
    extern __shared__ float sm[];
    float* ks   = sm;                  // [WND][DH]
    float* vs   = sm + WND * DH;       // [WND][DH]
    float* kinv = sm + 2 * WND * DH;   // [WND]

    const int bid = blockIdx.x;
    const int ib = bid & 31;
    const int h  = (bid >> 5) & (HEADS - 1);
    const int b  = bid >> 9;
    const int i0 = ib * TI;
    const int j0 = i0 - KOFF * DIL;    // may be negative

    const int tid  = threadIdx.x;
    const int wid  = tid >> 5;
    const int lane = tid & 31;

    // Cooperative load of k/v window (float4 granularity), OOB rows zeroed.
    #pragma unroll
    for (int u = tid; u < WND * (DH / 4); u += 256) {
        const int r  = u >> 4;
        const int c4 = (u & 15) * 4;
        const int j  = j0 + r;
        float4 kv4 = make_float4(0.f, 0.f, 0.f, 0.f);
        float4 vv4 = make_float4(0.f, 0.f, 0.f, 0.f);
        if (j >= 0 && j < NTOK) {
            const float* base = qkv + (size_t)(b * NTOK + j) * QKVCOLS + h * DH + c4;
            kv4 = *(const float4*)(base + DMODEL);
            vv4 = *(const float4*)(base + 2 * DMODEL);
        }
        *(float4*)(ks + r * DH + c4) = kv4;
        *(float4*)(vs + r * DH + c4) = vv4;
    }
    __syncthreads();

    // Per-row k-norms: warp w handles rows w, w+8, ...
    for (int r = wid; r < WND; r += 8) {
        const float2 kv = *(const float2*)(ks + r * DH + lane * 2);
        float kk = kv.x * kv.x + kv.y * kv.y;
        #pragma unroll
        for (int m = 16; m >= 1; m >>= 1)
            kk += __shfl_xor_sync(0xffffffffu, kk, m);
        if (lane == 0) kinv[r] = 1.0f / (sqrtf(kk) + EPSN);
    }
    __syncthreads();

    // 8 queries per warp
    #pragma unroll
    for (int qi = 0; qi < 8; qi++) {
        const int il = wid * 8 + qi;          // 0..63
        const int i  = i0 + il;

        const float2 q = *(const float2*)(
            qkv + (size_t)(b * NTOK + i) * QKVCOLS + h * DH + lane * 2);
        float qq = q.x * q.x + q.y * q.y;
        #pragma unroll
        for (int m = 16; m >= 1; m >>= 1)
            qq += __shfl_xor_sync(0xffffffffu, qq, m);
        const float qinv = 1.0f / (sqrtf(qq) + EPSN);

        float s[NOFF];
        #pragma unroll
        for (int t = 0; t < NOFF; t++) {
            const int j = i + (t - KOFF) * DIL;
            const int r = il + 2 * KOFF + (t - KOFF) * DIL;   // 0..95 always
            const float2 kv = *(const float2*)(ks + r * DH + lane * 2);
            float p = q.x * kv.x + q.y * kv.y;
            #pragma unroll
            for (int m = 16; m >= 1; m >>= 1)
                p += __shfl_xor_sync(0xffffffffu, p, m);
            s[t] = (j >= 0 && j < NTOK) ? p * qinv * kinv[r] : -1e30f;
        }

        float mx = s[0];
        #pragma unroll
        for (int t = 1; t < NOFF; t++) mx = fmaxf(mx, s[t]);

        float denom = 0.0f;
        #pragma unroll
        for (int t = 0; t < NOFF; t++) { s[t] = __expf(s[t] - mx); denom += s[t]; }
        const float inv = 1.0f / denom;

        float2 acc = make_float2(0.0f, 0.0f);
        #pragma unroll
        for (int t = 0; t < NOFF; t++) {
            const int r = il + 2 * KOFF + (t - KOFF) * DIL;
            const float2 v = *(const float2*)(vs + r * DH + lane * 2);
            const float ww = s[t] * inv;
            acc.x = fmaf(ww, v.x, acc.x);
            acc.y = fmaf(ww, v.y, acc.y);
        }

        const size_t o = (size_t)(b * NTOK + i) * DMODEL + h * DH + lane * 2;
        *(__half2*)(att + o) = __halves2half2(__float2half_rn(acc.x),
                                              __float2half_rn(acc.y));
    }
}

// ---------------------------------------------------------------------------
// Launch
// ---------------------------------------------------------------------------
extern "C" void kernel_launch(void* const* d_in, const int* in_sizes, int n_in,
                              void* d_out, int out_size)
{
    const float* x     = (const float*)d_in[0];
    const float* w_qkv = (const float*)d_in[1];
    const float* b_qkv = (const float*)d_in[2];
    const float* w_out = (const float*)d_in[3];
    const float* b_out = (const float*)d_in[4];
    float* out = (float*)d_out;

    float* qkv;
    __half *x16, *wq16, *wo16, *att16;
    cudaGetSymbolAddress((void**)&qkv,   g_qkv);
    cudaGetSymbolAddress((void**)&x16,   g_x16);
    cudaGetSymbolAddress((void**)&wq16,  g_wq16);
    cudaGetSymbolAddress((void**)&wo16,  g_wo16);
    cudaGetSymbolAddress((void**)&att16, g_att16);

    cudaFuncSetAttribute(gemm_hmma, cudaFuncAttributeMaxDynamicSharedMemorySize,
                         GEMM_SMEM);
    cudaFuncSetAttribute(attn_kernel, cudaFuncAttributeMaxDynamicSharedMemorySize,
                         ATT_SMEM);

    // fp32 -> fp16 rounds
    round_kernel<<<(MROWS * DMODEL) / 1024, 256>>>(x, x16, MROWS * DMODEL);
    round_kernel<<<(QKVCOLS * DMODEL) / 1024, 256>>>(w_qkv, wq16, QKVCOLS * DMODEL);
    round_kernel<<<(DMODEL * DMODEL) / 1024, 256>>>(w_out, wo16, DMODEL * DMODEL);

    // 1) QKV projection: [4096, 3072]
    {
        dim3 grid(QKVCOLS / BN, MROWS / BM);   // (24, 32)
        gemm_hmma<<<grid, 256, GEMM_SMEM>>>(x16, wq16, b_qkv, qkv, QKVCOLS);
    }
    // 2) Fused QK-norm + dilated attention (SMEM-tiled, writes fp16)
    attn_kernel<<<BATCH * HEADS * (NTOK / TI), 256, ATT_SMEM>>>(qkv, att16);
    // 3) Output projection: [4096, 1024]
    {
        dim3 grid(DMODEL / BN, MROWS / BM);    // (8, 32)
        gemm_hmma<<<grid, 256, GEMM_SMEM>>>(att16, wo16, b_out, out, DMODEL);
    }
}

// round 6
// speedup vs baseline: 5.3445x; 1.0245x over previous
#include <cuda_runtime.h>
#include <cuda_fp16.h>
#include <math.h>
#include <stdint.h>

// ---------------------------------------------------------------------------
// Problem constants
// ---------------------------------------------------------------------------
#define BATCH   2
#define NTOK    2048
#define DMODEL  1024
#define HEADS   16
#define DH      64
#define KOFF    8
#define DIL     2
#define NOFF    17
#define EPSN    1e-6f
#define MROWS   (BATCH * NTOK)       // 4096
#define QKVCOLS (3 * DMODEL)         // 3072
#define GK      1024                 // inner dim of both GEMMs

// ---------------------------------------------------------------------------
// Scratch (device globals; no runtime allocation allowed)
// ---------------------------------------------------------------------------
__device__ __align__(256) float   g_qkv[(size_t)MROWS * QKVCOLS];
__device__ __align__(256) __half  g_x16[(size_t)MROWS * DMODEL];
__device__ __align__(256) __half  g_wq16[(size_t)QKVCOLS * DMODEL];
__device__ __align__(256) __half  g_wo16[(size_t)DMODEL * DMODEL];
__device__ __align__(256) __half  g_att16[(size_t)MROWS * DMODEL];

// ---------------------------------------------------------------------------
// Inline PTX helpers (baseline sm_80+ ISA only)
// ---------------------------------------------------------------------------
__device__ __forceinline__ uint32_t s2u(const void* p) {
    uint32_t a;
    asm("{ .reg .u64 t; cvta.to.shared.u64 t, %1; cvt.u32.u64 %0, t; }"
        : "=r"(a) : "l"(p));
    return a;
}

__device__ __forceinline__ void cp16(uint32_t dst, const void* src) {
    asm volatile("cp.async.cg.shared.global [%0], [%1], 16;"
                 :: "r"(dst), "l"(src));
}
#define CP_COMMIT() asm volatile("cp.async.commit_group;")
#define CP_WAIT1()  asm volatile("cp.async.wait_group 1;")

__device__ __forceinline__ void ldsm4(uint32_t* r, uint32_t addr) {
    asm volatile("ldmatrix.sync.aligned.m8n8.x4.shared.b16 {%0,%1,%2,%3}, [%4];"
                 : "=r"(r[0]), "=r"(r[1]), "=r"(r[2]), "=r"(r[3]) : "r"(addr));
}

__device__ __forceinline__ void mma16816(float* c, const uint32_t* a,
                                         const uint32_t* b) {
    asm volatile(
        "mma.sync.aligned.m16n8k16.row.col.f32.f16.f16.f32 "
        "{%0,%1,%2,%3},{%4,%5,%6,%7},{%8,%9},{%0,%1,%2,%3};"
        : "+f"(c[0]), "+f"(c[1]), "+f"(c[2]), "+f"(c[3])
        : "r"(a[0]), "r"(a[1]), "r"(a[2]), "r"(a[3]), "r"(b[0]), "r"(b[1]));
}

#define SW128(x) ((x) ^ (((x) >> 3) & 0x70))

// ---------------------------------------------------------------------------
// Single-pass fp16 HMMA GEMM (NT): C[m,n] = sum_k A[m,k]*B[n,k] + bias[n]
// BM=128, BN=256, BK=64; 512 threads / 16 warps (64x32 warp tiles);
// 3-stage cp.async pipeline (prefetch depth 2), 144 KB SMEM.
// ---------------------------------------------------------------------------
#define BM 128
#define BN 256
#define BK 64
#define STAGES 3
#define NITER (GK / BK)              // 16
#define A_TILE_B (BM * 128)          // 16384
#define B_TILE_B (BN * 128)          // 32768
#define STAGE_B (A_TILE_B + B_TILE_B)   // 49152
#define GEMM_SMEM (STAGES * STAGE_B)    // 147456

__device__ __forceinline__ void load_stage(
    uint32_t sb, int s, const __half* __restrict__ A,
    const __half* __restrict__ Bw, int m0, int n0, int kc)
{
    const uint32_t base = sb + s * STAGE_B;
    // A tile: 128 rows x 8 chunks = 1024 cp.async
    #pragma unroll
    for (int u = threadIdx.x; u < BM * 8; u += 512) {
        const int r = u >> 3, ch = u & 7;
        const uint32_t sw = SW128((uint32_t)(r * 128 + ch * 16));
        cp16(base + sw, A + (size_t)(m0 + r) * GK + kc + ch * 8);
    }
    // B tile: 256 rows x 8 chunks = 2048 cp.async
    #pragma unroll
    for (int u = threadIdx.x; u < BN * 8; u += 512) {
        const int r = u >> 3, ch = u & 7;
        const uint32_t sw = SW128((uint32_t)(r * 128 + ch * 16));
        cp16(base + A_TILE_B + sw, Bw + (size_t)(n0 + r) * GK + kc + ch * 8);
    }
}

__global__ void __launch_bounds__(512, 1) gemm_hmma(
    const __half* __restrict__ A, const __half* __restrict__ Bw,
    const float* __restrict__ bias, float* __restrict__ C, int N)
{
    extern __shared__ char smem[];
    const uint32_t sb = s2u(smem);
    const int tid  = threadIdx.x;
    const int wid  = tid >> 5;
    const int lane = tid & 31;
    const int m0 = blockIdx.y * BM;
    const int n0 = blockIdx.x * BN;
    const int warp_m = (wid & 1) * 64;      // 2 m-warps
    const int warp_n = (wid >> 1) * 32;     // 8 n-warps

    // ldmatrix lane geometry (validated R3-R5)
    const int aRow = lane & 15;
    const int aKc  = (lane >> 4) & 1;
    const int bRow = ((lane >> 4) << 3) + (lane & 7);
    const int bK   = (lane >> 3) & 1;

    float acc[4][4][4];
    #pragma unroll
    for (int i = 0; i < 4; i++)
        #pragma unroll
        for (int j = 0; j < 4; j++)
            #pragma unroll
            for (int q = 0; q < 4; q++) acc[i][j][q] = 0.0f;

    load_stage(sb, 0, A, Bw, m0, n0, 0);   CP_COMMIT();
    load_stage(sb, 1, A, Bw, m0, n0, BK);  CP_COMMIT();

    for (int it = 0; it < NITER; it++) {
        CP_WAIT1();
        __syncthreads();
        if (it + 2 < NITER) {
            int s = it + 2; while (s >= STAGES) s -= STAGES;
            load_stage(sb, s, A, Bw, m0, n0, (it + 2) * BK);
        }
        CP_COMMIT();

        int cs = it; while (cs >= STAGES) cs -= STAGES;
        const uint32_t Ab = sb + cs * STAGE_B;
        const uint32_t Bb = Ab + A_TILE_B;

        #pragma unroll
        for (int ks = 0; ks < 4; ks++) {
            uint32_t bfr[2][4];
            #pragma unroll
            for (int nt2 = 0; nt2 < 2; nt2++) {
                const uint32_t off = (uint32_t)((warp_n + nt2 * 16 + bRow) * 128
                                                + ks * 32 + bK * 16);
                ldsm4(bfr[nt2], Bb + SW128(off));
            }
            uint32_t ah[4][4];
            #pragma unroll
            for (int mt = 0; mt < 4; mt++) {
                const uint32_t off = (uint32_t)((warp_m + mt * 16 + aRow) * 128
                                                + ks * 32 + aKc * 16);
                ldsm4(ah[mt], Ab + SW128(off));
            }
            #pragma unroll
            for (int mt = 0; mt < 4; mt++)
                #pragma unroll
                for (int nt = 0; nt < 4; nt++)
                    mma16816(acc[mt][nt], ah[mt], &bfr[nt >> 1][(nt & 1) * 2]);
        }
    }

    // Epilogue: fused bias, float2 stores
    const int lr = lane >> 2;
    const int lc = (lane & 3) * 2;
    #pragma unroll
    for (int mt = 0; mt < 4; mt++) {
        #pragma unroll
        for (int nt = 0; nt < 4; nt++) {
            const int col = n0 + warp_n + nt * 8 + lc;
            const float2 bi = *(const float2*)(bias + col);
            const int row0 = m0 + warp_m + mt * 16 + lr;
            float2 v0 = make_float2(acc[mt][nt][0] + bi.x, acc[mt][nt][1] + bi.y);
            float2 v1 = make_float2(acc[mt][nt][2] + bi.x, acc[mt][nt][3] + bi.y);
            *(float2*)(C + (size_t)row0 * N + col) = v0;
            *(float2*)(C + (size_t)(row0 + 8) * N + col) = v1;
        }
    }
}

// ---------------------------------------------------------------------------
// fp32 -> fp16 round
// ---------------------------------------------------------------------------
__global__ void __launch_bounds__(256) round_kernel(
    const float* __restrict__ s, __half* __restrict__ d, int n)
{
    int i = (blockIdx.x * 256 + threadIdx.x) * 4;
    if (i >= n) return;
    float4 v = *(const float4*)(s + i);
    union { __half h[4]; uint2 u; } H = {{__float2half_rn(v.x), __float2half_rn(v.y),
                                          __float2half_rn(v.z), __float2half_rn(v.w)}};
    *(uint2*)(d + i) = H.u;
}

// ---------------------------------------------------------------------------
// Fused QK-norm + dilated attention, SMEM-tiled (validated R5).
// Block = 64 consecutive queries for one (b, h); 96-row k/v window staged
// in SMEM, per-row k-norms computed once. Output rounded to fp16.
// ---------------------------------------------------------------------------
#define TI   64
#define WND  (TI + 2 * KOFF * DIL)    // 96
#define ATT_SMEM ((2 * WND * DH + WND) * 4)

__global__ void __launch_bounds__(256, 1) attn_kernel(
    const float* __restrict__ qkv, __half* __restrict__ att)
{
    extern __shared__ float sm[];
    float* ks   = sm;
    float* vs   = sm + WND * DH;
    float* kinv = sm + 2 * WND * DH;

    const int bid = blockIdx.x;
    const int ib = bid & 31;
    const int h  = (bid >> 5) & (HEADS - 1);
    const int b  = bid >> 9;
    const int i0 = ib * TI;
    const int j0 = i0 - KOFF * DIL;

    const int tid  = threadIdx.x;
    const int wid  = tid >> 5;
    const int lane = tid & 31;

    #pragma unroll
    for (int u = tid; u < WND * (DH / 4); u += 256) {
        const int r  = u >> 4;
        const int c4 = (u & 15) * 4;
        const int j  = j0 + r;
        float4 kv4 = make_float4(0.f, 0.f, 0.f, 0.f);
        float4 vv4 = make_float4(0.f, 0.f, 0.f, 0.f);
        if (j >= 0 && j < NTOK) {
            const float* base = qkv + (size_t)(b * NTOK + j) * QKVCOLS + h * DH + c4;
            kv4 = *(const float4*)(base + DMODEL);
            vv4 = *(const float4*)(base + 2 * DMODEL);
        }
        *(float4*)(ks + r * DH + c4) = kv4;
        *(float4*)(vs + r * DH + c4) = vv4;
    }
    __syncthreads();

    for (int r = wid; r < WND; r += 8) {
        const float2 kv = *(const float2*)(ks + r * DH + lane * 2);
        float kk = kv.x * kv.x + kv.y * kv.y;
        #pragma unroll
        for (int m = 16; m >= 1; m >>= 1)
            kk += __shfl_xor_sync(0xffffffffu, kk, m);
        if (lane == 0) kinv[r] = 1.0f / (sqrtf(kk) + EPSN);
    }
    __syncthreads();

    #pragma unroll
    for (int qi = 0; qi < 8; qi++) {
        const int il = wid * 8 + qi;
        const int i  = i0 + il;

        const float2 q = *(const float2*)(
            qkv + (size_t)(b * NTOK + i) * QKVCOLS + h * DH + lane * 2);
        float qq = q.x * q.x + q.y * q.y;
        #pragma unroll
        for (int m = 16; m >= 1; m >>= 1)
            qq += __shfl_xor_sync(0xffffffffu, qq, m);
        const float qinv = 1.0f / (sqrtf(qq) + EPSN);

        float s[NOFF];
        #pragma unroll
        for (int t = 0; t < NOFF; t++) {
            const int j = i + (t - KOFF) * DIL;
            const int r = il + 2 * KOFF + (t - KOFF) * DIL;
            const float2 kv = *(const float2*)(ks + r * DH + lane * 2);
            float p = q.x * kv.x + q.y * kv.y;
            #pragma unroll
            for (int m = 16; m >= 1; m >>= 1)
                p += __shfl_xor_sync(0xffffffffu, p, m);
            s[t] = (j >= 0 && j < NTOK) ? p * qinv * kinv[r] : -1e30f;
        }

        float mx = s[0];
        #pragma unroll
        for (int t = 1; t < NOFF; t++) mx = fmaxf(mx, s[t]);

        float denom = 0.0f;
        #pragma unroll
        for (int t = 0; t < NOFF; t++) { s[t] = __expf(s[t] - mx); denom += s[t]; }
        const float inv = 1.0f / denom;

        float2 acc = make_float2(0.0f, 0.0f);
        #pragma unroll
        for (int t = 0; t < NOFF; t++) {
            const int r = il + 2 * KOFF + (t - KOFF) * DIL;
            const float2 v = *(const float2*)(vs + r * DH + lane * 2);
            const float ww = s[t] * inv;
            acc.x = fmaf(ww, v.x, acc.x);
            acc.y = fmaf(ww, v.y, acc.y);
        }

        const size_t o = (size_t)(b * NTOK + i) * DMODEL + h * DH + lane * 2;
        *(__half2*)(att + o) = __halves2half2(__float2half_rn(acc.x),
                                              __float2half_rn(acc.y));
    }
}

// ---------------------------------------------------------------------------
// Launch
// ---------------------------------------------------------------------------
extern "C" void kernel_launch(void* const* d_in, const int* in_sizes, int n_in,
                              void* d_out, int out_size)
{
    const float* x     = (const float*)d_in[0];
    const float* w_qkv = (const float*)d_in[1];
    const float* b_qkv = (const float*)d_in[2];
    const float* w_out = (const float*)d_in[3];
    const float* b_out = (const float*)d_in[4];
    float* out = (float*)d_out;

    float* qkv;
    __half *x16, *wq16, *wo16, *att16;
    cudaGetSymbolAddress((void**)&qkv,   g_qkv);
    cudaGetSymbolAddress((void**)&x16,   g_x16);
    cudaGetSymbolAddress((void**)&wq16,  g_wq16);
    cudaGetSymbolAddress((void**)&wo16,  g_wo16);
    cudaGetSymbolAddress((void**)&att16, g_att16);

    cudaFuncSetAttribute(gemm_hmma, cudaFuncAttributeMaxDynamicSharedMemorySize,
                         GEMM_SMEM);
    cudaFuncSetAttribute(attn_kernel, cudaFuncAttributeMaxDynamicSharedMemorySize,
                         ATT_SMEM);

    // fp32 -> fp16 rounds
    round_kernel<<<(MROWS * DMODEL) / 1024, 256>>>(x, x16, MROWS * DMODEL);
    round_kernel<<<(QKVCOLS * DMODEL) / 1024, 256>>>(w_qkv, wq16, QKVCOLS * DMODEL);
    round_kernel<<<(DMODEL * DMODEL) / 1024, 256>>>(w_out, wo16, DMODEL * DMODEL);

    // 1) QKV projection: [4096, 3072]
    {
        dim3 grid(QKVCOLS / BN, MROWS / BM);   // (12, 32)
        gemm_hmma<<<grid, 512, GEMM_SMEM>>>(x16, wq16, b_qkv, qkv, QKVCOLS);
    }
    // 2) Fused QK-norm + dilated attention (SMEM-tiled, writes fp16)
    attn_kernel<<<BATCH * HEADS * (NTOK / TI), 256, ATT_SMEM>>>(qkv, att16);
    // 3) Output projection: [4096, 1024]
    {
        dim3 grid(DMODEL / BN, MROWS / BM);    // (4, 32)
        gemm_hmma<<<grid, 512, GEMM_SMEM>>>(att16, wo16, b_out, out, DMODEL);
    }
}

// round 7
// speedup vs baseline: 5.9293x; 1.1094x over previous
#include <cuda_runtime.h>
#include <cuda_fp16.h>
#include <math.h>
#include <stdint.h>

// ---------------------------------------------------------------------------
// Problem constants
// ---------------------------------------------------------------------------
#define BATCH   2
#define NTOK    2048
#define DMODEL  1024
#define HEADS   16
#define DH      64
#define KOFF    8
#define DIL     2
#define NOFF    17
#define EPSN    1e-6f
#define MROWS   (BATCH * NTOK)       // 4096
#define QKVCOLS (3 * DMODEL)         // 3072
#define GK      1024                 // inner dim of both GEMMs

// ---------------------------------------------------------------------------
// Scratch (device globals; no runtime allocation allowed)
// ---------------------------------------------------------------------------
__device__ __align__(256) float   g_qkv[(size_t)MROWS * QKVCOLS];
__device__ __align__(256) __half  g_x16[(size_t)MROWS * DMODEL];
__device__ __align__(256) __half  g_wq16[(size_t)QKVCOLS * DMODEL];
__device__ __align__(256) __half  g_wo16[(size_t)DMODEL * DMODEL];
__device__ __align__(256) __half  g_att16[(size_t)MROWS * DMODEL];

// ---------------------------------------------------------------------------
// Inline PTX helpers (baseline sm_80+ ISA only)
// ---------------------------------------------------------------------------
__device__ __forceinline__ uint32_t s2u(const void* p) {
    uint32_t a;
    asm("{ .reg .u64 t; cvta.to.shared.u64 t, %1; cvt.u32.u64 %0, t; }"
        : "=r"(a) : "l"(p));
    return a;
}

__device__ __forceinline__ void cp16(uint32_t dst, const void* src) {
    asm volatile("cp.async.cg.shared.global [%0], [%1], 16;"
                 :: "r"(dst), "l"(src));
}
#define CP_COMMIT() asm volatile("cp.async.commit_group;")
#define CP_WAIT2()  asm volatile("cp.async.wait_group 2;")

__device__ __forceinline__ void ldsm4(uint32_t* r, uint32_t addr) {
    asm volatile("ldmatrix.sync.aligned.m8n8.x4.shared.b16 {%0,%1,%2,%3}, [%4];"
                 : "=r"(r[0]), "=r"(r[1]), "=r"(r[2]), "=r"(r[3]) : "r"(addr));
}

__device__ __forceinline__ void mma16816(float* c, const uint32_t* a,
                                         const uint32_t* b) {
    asm volatile(
        "mma.sync.aligned.m16n8k16.row.col.f32.f16.f16.f32 "
        "{%0,%1,%2,%3},{%4,%5,%6,%7},{%8,%9},{%0,%1,%2,%3};"
        : "+f"(c[0]), "+f"(c[1]), "+f"(c[2]), "+f"(c[3])
        : "r"(a[0]), "r"(a[1]), "r"(a[2]), "r"(a[3]), "r"(b[0]), "r"(b[1]));
}

#define SW128(x) ((x) ^ (((x) >> 3) & 0x70))

// ---------------------------------------------------------------------------
// Single-pass fp16 HMMA GEMM (NT): C[m,n] = sum_k A[m,k]*B[n,k] + bias[n]
// BM=128, BN=256, BK=64; 512 threads / 16 warps (64x32 warp tiles);
// 4-stage cp.async pipeline (prefetch depth 3), 196.6 KB SMEM.
// Mainloop uses incremental pointers + decomposed SW128 addressing.
// ---------------------------------------------------------------------------
#define BM 128
#define BN 256
#define BK 64
#define STAGES 4
#define NITER (GK / BK)              // 16
#define A_TILE_B (BM * 128)          // 16384
#define B_TILE_B (BN * 128)          // 32768
#define STAGE_B (A_TILE_B + B_TILE_B)   // 49152
#define GEMM_SMEM (STAGES * STAGE_B)    // 196608

__global__ void __launch_bounds__(512, 1) gemm_hmma(
    const __half* __restrict__ A, const __half* __restrict__ Bw,
    const float* __restrict__ bias, float* __restrict__ C, int N)
{
    extern __shared__ char smem[];
    const uint32_t sb = s2u(smem);
    const int tid  = threadIdx.x;
    const int wid  = tid >> 5;
    const int lane = tid & 31;
    const int m0 = blockIdx.y * BM;
    const int n0 = blockIdx.x * BN;
    const int warp_m = (wid & 1) * 64;      // 2 m-warps
    const int warp_n = (wid >> 1) * 32;     // 8 n-warps

    // ---- per-thread load geometry (computed ONCE) ----
    const int lr  = tid >> 3;               // 0..63
    const int lch = tid & 7;                // 16B chunk
    const __half* pA = A  + (size_t)(m0 + lr) * GK + lch * 8;  // rows lr, lr+64
    const __half* pB = Bw + (size_t)(n0 + lr) * GK + lch * 8;  // rows lr..lr+192
    const size_t rskip = (size_t)64 * GK;
    const uint32_t swA0 = SW128((uint32_t)(lr * 128 + lch * 16));
    const uint32_t swA1 = SW128((uint32_t)((lr + 64) * 128 + lch * 16));
    const uint32_t swB2 = SW128((uint32_t)((lr + 128) * 128 + lch * 16));
    const uint32_t swB3 = SW128((uint32_t)((lr + 192) * 128 + lch * 16));

    // ---- ldmatrix geometry: decomposed SW128 (mask depends on row only) ----
    const int aRow = lane & 15;
    const int aKc  = (lane >> 4) & 1;
    const int bRow = ((lane >> 4) << 3) + (lane & 7);
    const int bK   = (lane >> 3) & 1;

    uint32_t aRB[4], aMask[4];
    #pragma unroll
    for (int mt = 0; mt < 4; mt++) {
        aRB[mt]   = (uint32_t)((warp_m + mt * 16 + aRow) * 128);
        aMask[mt] = (aRB[mt] >> 3) & 0x70;
    }
    uint32_t bRB[2], bMask[2];
    #pragma unroll
    for (int nt2 = 0; nt2 < 2; nt2++) {
        bRB[nt2]   = (uint32_t)((warp_n + nt2 * 16 + bRow) * 128);
        bMask[nt2] = (bRB[nt2] >> 3) & 0x70;
    }
    const uint32_t aCol = (uint32_t)(aKc * 16);
    const uint32_t bCol = (uint32_t)(bK * 16);

    float acc[4][4][4];
    #pragma unroll
    for (int i = 0; i < 4; i++)
        #pragma unroll
        for (int j = 0; j < 4; j++)
            #pragma unroll
            for (int q = 0; q < 4; q++) acc[i][j][q] = 0.0f;

    // ---- stage loader: constant smem offsets, pointer + kc only ----
    auto load_stage = [&](uint32_t base, int kc) {
        cp16(base + swA0, pA + kc);
        cp16(base + swA1, pA + rskip + kc);
        const uint32_t bb = base + A_TILE_B;
        cp16(bb + swA0, pB + kc);
        cp16(bb + swA1, pB + rskip + kc);
        cp16(bb + swB2, pB + 2 * rskip + kc);
        cp16(bb + swB3, pB + 3 * rskip + kc);
    };

    load_stage(sb, 0);                       CP_COMMIT();
    load_stage(sb + STAGE_B, BK);            CP_COMMIT();
    load_stage(sb + 2 * STAGE_B, 2 * BK);    CP_COMMIT();

    #pragma unroll 4
    for (int it = 0; it < NITER; it++) {
        CP_WAIT2();
        __syncthreads();
        if (it + 3 < NITER)
            load_stage(sb + ((it + 3) & 3) * STAGE_B, (it + 3) * BK);
        CP_COMMIT();

        const uint32_t Ab = sb + (it & 3) * STAGE_B;
        const uint32_t Bb = Ab + A_TILE_B;

        #pragma unroll
        for (int ks = 0; ks < 4; ks++) {
            const uint32_t kb = (uint32_t)(ks * 32);
            uint32_t bfr[2][4];
            #pragma unroll
            for (int nt2 = 0; nt2 < 2; nt2++)
                ldsm4(bfr[nt2], Bb + bRB[nt2] + ((kb + bCol) ^ bMask[nt2]));
            uint32_t ah[4][4];
            #pragma unroll
            for (int mt = 0; mt < 4; mt++)
                ldsm4(ah[mt], Ab + aRB[mt] + ((kb + aCol) ^ aMask[mt]));
            #pragma unroll
            for (int mt = 0; mt < 4; mt++)
                #pragma unroll
                for (int nt = 0; nt < 4; nt++)
                    mma16816(acc[mt][nt], ah[mt], &bfr[nt >> 1][(nt & 1) * 2]);
        }
    }

    // Epilogue: fused bias, float2 stores
    const int elr = lane >> 2;
    const int elc = (lane & 3) * 2;
    #pragma unroll
    for (int mt = 0; mt < 4; mt++) {
        #pragma unroll
        for (int nt = 0; nt < 4; nt++) {
            const int col = n0 + warp_n + nt * 8 + elc;
            const float2 bi = *(const float2*)(bias + col);
            const int row0 = m0 + warp_m + mt * 16 + elr;
            float2 v0 = make_float2(acc[mt][nt][0] + bi.x, acc[mt][nt][1] + bi.y);
            float2 v1 = make_float2(acc[mt][nt][2] + bi.x, acc[mt][nt][3] + bi.y);
            *(float2*)(C + (size_t)row0 * N + col) = v0;
            *(float2*)(C + (size_t)(row0 + 8) * N + col) = v1;
        }
    }
}

// ---------------------------------------------------------------------------
// fp32 -> fp16 round
// ---------------------------------------------------------------------------
__global__ void __launch_bounds__(256) round_kernel(
    const float* __restrict__ s, __half* __restrict__ d, int n)
{
    int i = (blockIdx.x * 256 + threadIdx.x) * 4;
    if (i >= n) return;
    float4 v = *(const float4*)(s + i);
    union { __half h[4]; uint2 u; } H = {{__float2half_rn(v.x), __float2half_rn(v.y),
                                          __float2half_rn(v.z), __float2half_rn(v.w)}};
    *(uint2*)(d + i) = H.u;
}

// ---------------------------------------------------------------------------
// Fused QK-norm + dilated attention, SMEM-tiled (validated R5/R6).
// ---------------------------------------------------------------------------
#define TI   64
#define WND  (TI + 2 * KOFF * DIL)    // 96
#define ATT_SMEM ((2 * WND * DH + WND) * 4)

__global__ void __launch_bounds__(256, 1) attn_kernel(
    const float* __restrict__ qkv, __half* __restrict__ att)
{
    extern __shared__ float sm[];
    float* ks   = sm;
    float* vs   = sm + WND * DH;
    float* kinv = sm + 2 * WND * DH;

    const int bid = blockIdx.x;
    const int ib = bid & 31;
    const int h  = (bid >> 5) & (HEADS - 1);
    const int b  = bid >> 9;
    const int i0 = ib * TI;
    const int j0 = i0 - KOFF * DIL;

    const int tid  = threadIdx.x;
    const int wid  = tid >> 5;
    const int lane = tid & 31;

    #pragma unroll
    for (int u = tid; u < WND * (DH / 4); u += 256) {
        const int r  = u >> 4;
        const int c4 = (u & 15) * 4;
        const int j  = j0 + r;
        float4 kv4 = make_float4(0.f, 0.f, 0.f, 0.f);
        float4 vv4 = make_float4(0.f, 0.f, 0.f, 0.f);
        if (j >= 0 && j < NTOK) {
            const float* base = qkv + (size_t)(b * NTOK + j) * QKVCOLS + h * DH + c4;
            kv4 = *(const float4*)(base + DMODEL);
            vv4 = *(const float4*)(base + 2 * DMODEL);
        }
        *(float4*)(ks + r * DH + c4) = kv4;
        *(float4*)(vs + r * DH + c4) = vv4;
    }
    __syncthreads();

    for (int r = wid; r < WND; r += 8) {
        const float2 kv = *(const float2*)(ks + r * DH + lane * 2);
        float kk = kv.x * kv.x + kv.y * kv.y;
        #pragma unroll
        for (int m = 16; m >= 1; m >>= 1)
            kk += __shfl_xor_sync(0xffffffffu, kk, m);
        if (lane == 0) kinv[r] = 1.0f / (sqrtf(kk) + EPSN);
    }
    __syncthreads();

    #pragma unroll
    for (int qi = 0; qi < 8; qi++) {
        const int il = wid * 8 + qi;
        const int i  = i0 + il;

        const float2 q = *(const float2*)(
            qkv + (size_t)(b * NTOK + i) * QKVCOLS + h * DH + lane * 2);
        float qq = q.x * q.x + q.y * q.y;
        #pragma unroll
        for (int m = 16; m >= 1; m >>= 1)
            qq += __shfl_xor_sync(0xffffffffu, qq, m);
        const float qinv = 1.0f / (sqrtf(qq) + EPSN);

        float s[NOFF];
        #pragma unroll
        for (int t = 0; t < NOFF; t++) {
            const int j = i + (t - KOFF) * DIL;
            const int r = il + 2 * KOFF + (t - KOFF) * DIL;
            const float2 kv = *(const float2*)(ks + r * DH + lane * 2);
            float p = q.x * kv.x + q.y * kv.y;
            #pragma unroll
            for (int m = 16; m >= 1; m >>= 1)
                p += __shfl_xor_sync(0xffffffffu, p, m);
            s[t] = (j >= 0 && j < NTOK) ? p * qinv * kinv[r] : -1e30f;
        }

        float mx = s[0];
        #pragma unroll
        for (int t = 1; t < NOFF; t++) mx = fmaxf(mx, s[t]);

        float denom = 0.0f;
        #pragma unroll
        for (int t = 0; t < NOFF; t++) { s[t] = __expf(s[t] - mx); denom += s[t]; }
        const float inv = 1.0f / denom;

        float2 acc = make_float2(0.0f, 0.0f);
        #pragma unroll
        for (int t = 0; t < NOFF; t++) {
            const int r = il + 2 * KOFF + (t - KOFF) * DIL;
            const float2 v = *(const float2*)(vs + r * DH + lane * 2);
            const float ww = s[t] * inv;
            acc.x = fmaf(ww, v.x, acc.x);
            acc.y = fmaf(ww, v.y, acc.y);
        }

        const size_t o = (size_t)(b * NTOK + i) * DMODEL + h * DH + lane * 2;
        *(__half2*)(att + o) = __halves2half2(__float2half_rn(acc.x),
                                              __float2half_rn(acc.y));
    }
}

// ---------------------------------------------------------------------------
// Launch
// ---------------------------------------------------------------------------
extern "C" void kernel_launch(void* const* d_in, const int* in_sizes, int n_in,
                              void* d_out, int out_size)
{
    const float* x     = (const float*)d_in[0];
    const float* w_qkv = (const float*)d_in[1];
    const float* b_qkv = (const float*)d_in[2];
    const float* w_out = (const float*)d_in[3];
    const float* b_out = (const float*)d_in[4];
    float* out = (float*)d_out;

    float* qkv;
    __half *x16, *wq16, *wo16, *att16;
    cudaGetSymbolAddress((void**)&qkv,   g_qkv);
    cudaGetSymbolAddress((void**)&x16,   g_x16);
    cudaGetSymbolAddress((void**)&wq16,  g_wq16);
    cudaGetSymbolAddress((void**)&wo16,  g_wo16);
    cudaGetSymbolAddress((void**)&att16, g_att16);

    cudaFuncSetAttribute(gemm_hmma, cudaFuncAttributeMaxDynamicSharedMemorySize,
                         GEMM_SMEM);
    cudaFuncSetAttribute(attn_kernel, cudaFuncAttributeMaxDynamicSharedMemorySize,
                         ATT_SMEM);

    // fp32 -> fp16 rounds
    round_kernel<<<(MROWS * DMODEL) / 1024, 256>>>(x, x16, MROWS * DMODEL);
    round_kernel<<<(QKVCOLS * DMODEL) / 1024, 256>>>(w_qkv, wq16, QKVCOLS * DMODEL);
    round_kernel<<<(DMODEL * DMODEL) / 1024, 256>>>(w_out, wo16, DMODEL * DMODEL);

    // 1) QKV projection: [4096, 3072]
    {
        dim3 grid(QKVCOLS / BN, MROWS / BM);   // (12, 32)
        gemm_hmma<<<grid, 512, GEMM_SMEM>>>(x16, wq16, b_qkv, qkv, QKVCOLS);
    }
    // 2) Fused QK-norm + dilated attention (SMEM-tiled, writes fp16)
    attn_kernel<<<BATCH * HEADS * (NTOK / TI), 256, ATT_SMEM>>>(qkv, att16);
    // 3) Output projection: [4096, 1024]
    {
        dim3 grid(DMODEL / BN, MROWS / BM);    // (4, 32)
        gemm_hmma<<<grid, 512, GEMM_SMEM>>>(att16, wo16, b_out, out, DMODEL);
    }
}

// round 8
// speedup vs baseline: 6.1179x; 1.0318x over previous
#include <cuda_runtime.h>
#include <cuda_fp16.h>
#include <math.h>
#include <stdint.h>

// ---------------------------------------------------------------------------
// Problem constants
// ---------------------------------------------------------------------------
#define BATCH   2
#define NTOK    2048
#define DMODEL  1024
#define HEADS   16
#define DH      64
#define KOFF    8
#define DIL     2
#define NOFF    17
#define EPSN    1e-6f
#define MROWS   (BATCH * NTOK)       // 4096
#define QKVCOLS (3 * DMODEL)         // 3072
#define GK      1024                 // inner dim of both GEMMs

// ---------------------------------------------------------------------------
// Scratch (device globals; no runtime allocation allowed)
// ---------------------------------------------------------------------------
__device__ __align__(256) float   g_qkv[(size_t)MROWS * QKVCOLS];
__device__ __align__(256) __half  g_x16[(size_t)MROWS * DMODEL];
__device__ __align__(256) __half  g_wq16[(size_t)QKVCOLS * DMODEL];
__device__ __align__(256) __half  g_wo16[(size_t)DMODEL * DMODEL];
__device__ __align__(256) __half  g_att16[(size_t)MROWS * DMODEL];

// ---------------------------------------------------------------------------
// Inline PTX helpers (baseline sm_80+ ISA only)
// ---------------------------------------------------------------------------
__device__ __forceinline__ uint32_t s2u(const void* p) {
    uint32_t a;
    asm("{ .reg .u64 t; cvta.to.shared.u64 t, %1; cvt.u32.u64 %0, t; }"
        : "=r"(a) : "l"(p));
    return a;
}

__device__ __forceinline__ void cp16(uint32_t dst, const void* src) {
    asm volatile("cp.async.cg.shared.global [%0], [%1], 16;"
                 :: "r"(dst), "l"(src));
}
#define CP_COMMIT() asm volatile("cp.async.commit_group;")
#define CP_WAIT2()  asm volatile("cp.async.wait_group 2;")

__device__ __forceinline__ void ldsm4(uint32_t* r, uint32_t addr) {
    asm volatile("ldmatrix.sync.aligned.m8n8.x4.shared.b16 {%0,%1,%2,%3}, [%4];"
                 : "=r"(r[0]), "=r"(r[1]), "=r"(r[2]), "=r"(r[3]) : "r"(addr));
}

__device__ __forceinline__ void mma16816(float* c, const uint32_t* a,
                                         const uint32_t* b) {
    asm volatile(
        "mma.sync.aligned.m16n8k16.row.col.f32.f16.f16.f32 "
        "{%0,%1,%2,%3},{%4,%5,%6,%7},{%8,%9},{%0,%1,%2,%3};"
        : "+f"(c[0]), "+f"(c[1]), "+f"(c[2]), "+f"(c[3])
        : "r"(a[0]), "r"(a[1]), "r"(a[2]), "r"(a[3]), "r"(b[0]), "r"(b[1]));
}

#define SW128(x) ((x) ^ (((x) >> 3) & 0x70))

// ---------------------------------------------------------------------------
// Single-pass fp16 HMMA GEMM (NT): C[m,n] = sum_k A[m,k]*B[n,k] + bias[n]
// BM=128, BN=256, BK=64; 256 threads / 8 warps; 64x64 warp tiles
// (MMA:ldsm = 4.0 -> smem crossbar supports ~89% of HMMA peak).
// 4-stage cp.async pipeline (prefetch depth 3), 192 KB SMEM.
// ---------------------------------------------------------------------------
#define BM 128
#define BN 256
#define BK 64
#define STAGES 4
#define NITER (GK / BK)              // 16
#define A_TILE_B (BM * 128)          // 16384
#define B_TILE_B (BN * 128)          // 32768
#define STAGE_B (A_TILE_B + B_TILE_B)   // 49152
#define GEMM_SMEM (STAGES * STAGE_B)    // 196608

__global__ void __launch_bounds__(256, 1) gemm_hmma(
    const __half* __restrict__ A, const __half* __restrict__ Bw,
    const float* __restrict__ bias, float* __restrict__ C, int N)
{
    extern __shared__ char smem[];
    const uint32_t sb = s2u(smem);
    const int tid  = threadIdx.x;
    const int wid  = tid >> 5;
    const int lane = tid & 31;
    const int m0 = blockIdx.y * BM;
    const int n0 = blockIdx.x * BN;
    const int warp_m = (wid & 1) * 64;      // 2 m-warps
    const int warp_n = (wid >> 1) * 64;     // 4 n-warps

    // ---- per-thread load geometry (computed ONCE): 256 thr -> 32 rows/pass
    const int lr  = tid >> 3;               // 0..31
    const int lch = tid & 7;                // 16B chunk
    const __half* pA = A  + (size_t)(m0 + lr) * GK + lch * 8;
    const __half* pB = Bw + (size_t)(n0 + lr) * GK + lch * 8;
    const size_t rskip = (size_t)32 * GK;
    uint32_t swA[4], swB[8];
    #pragma unroll
    for (int i = 0; i < 4; i++)
        swA[i] = SW128((uint32_t)((lr + 32 * i) * 128 + lch * 16));
    #pragma unroll
    for (int i = 0; i < 8; i++)
        swB[i] = SW128((uint32_t)((lr + 32 * i) * 128 + lch * 16));

    // ---- ldmatrix geometry: decomposed SW128 (mask depends on row only) ----
    const int aRow = lane & 15;
    const int aKc  = (lane >> 4) & 1;
    const int bRow = ((lane >> 4) << 3) + (lane & 7);
    const int bK   = (lane >> 3) & 1;

    uint32_t aRB[4], aMask[4];
    #pragma unroll
    for (int mt = 0; mt < 4; mt++) {
        aRB[mt]   = (uint32_t)((warp_m + mt * 16 + aRow) * 128);
        aMask[mt] = (aRB[mt] >> 3) & 0x70;
    }
    uint32_t bRB[4], bMask[4];
    #pragma unroll
    for (int nt2 = 0; nt2 < 4; nt2++) {
        bRB[nt2]   = (uint32_t)((warp_n + nt2 * 16 + bRow) * 128);
        bMask[nt2] = (bRB[nt2] >> 3) & 0x70;
    }
    const uint32_t aCol = (uint32_t)(aKc * 16);
    const uint32_t bCol = (uint32_t)(bK * 16);

    float acc[4][8][4];
    #pragma unroll
    for (int i = 0; i < 4; i++)
        #pragma unroll
        for (int j = 0; j < 8; j++)
            #pragma unroll
            for (int q = 0; q < 4; q++) acc[i][j][q] = 0.0f;

    // ---- stage loader: constant smem offsets, pointer + kc only ----
    auto load_stage = [&](uint32_t base, int kc) {
        #pragma unroll
        for (int i = 0; i < 4; i++)
            cp16(base + swA[i], pA + i * rskip + kc);
        const uint32_t bb = base + A_TILE_B;
        #pragma unroll
        for (int i = 0; i < 8; i++)
            cp16(bb + swB[i], pB + i * rskip + kc);
    };

    load_stage(sb, 0);                       CP_COMMIT();
    load_stage(sb + STAGE_B, BK);            CP_COMMIT();
    load_stage(sb + 2 * STAGE_B, 2 * BK);    CP_COMMIT();

    #pragma unroll 4
    for (int it = 0; it < NITER; it++) {
        CP_WAIT2();
        __syncthreads();
        if (it + 3 < NITER)
            load_stage(sb + ((it + 3) & 3) * STAGE_B, (it + 3) * BK);
        CP_COMMIT();

        const uint32_t Ab = sb + (it & 3) * STAGE_B;
        const uint32_t Bb = Ab + A_TILE_B;

        #pragma unroll
        for (int ks = 0; ks < 4; ks++) {
            const uint32_t kb = (uint32_t)(ks * 32);
            uint32_t bfr[4][4];
            #pragma unroll
            for (int nt2 = 0; nt2 < 4; nt2++)
                ldsm4(bfr[nt2], Bb + bRB[nt2] + ((kb + bCol) ^ bMask[nt2]));
            uint32_t ah[4][4];
            #pragma unroll
            for (int mt = 0; mt < 4; mt++)
                ldsm4(ah[mt], Ab + aRB[mt] + ((kb + aCol) ^ aMask[mt]));
            #pragma unroll
            for (int mt = 0; mt < 4; mt++)
                #pragma unroll
                for (int nt = 0; nt < 8; nt++)
                    mma16816(acc[mt][nt], ah[mt], &bfr[nt >> 1][(nt & 1) * 2]);
        }
    }

    // Epilogue: fused bias, float2 stores
    const int elr = lane >> 2;
    const int elc = (lane & 3) * 2;
    #pragma unroll
    for (int mt = 0; mt < 4; mt++) {
        #pragma unroll
        for (int nt = 0; nt < 8; nt++) {
            const int col = n0 + warp_n + nt * 8 + elc;
            const float2 bi = *(const float2*)(bias + col);
            const int row0 = m0 + warp_m + mt * 16 + elr;
            float2 v0 = make_float2(acc[mt][nt][0] + bi.x, acc[mt][nt][1] + bi.y);
            float2 v1 = make_float2(acc[mt][nt][2] + bi.x, acc[mt][nt][3] + bi.y);
            *(float2*)(C + (size_t)row0 * N + col) = v0;
            *(float2*)(C + (size_t)(row0 + 8) * N + col) = v1;
        }
    }
}

// ---------------------------------------------------------------------------
// Fused fp32 -> fp16 rounding of x, w_qkv, w_out in ONE launch.
// ---------------------------------------------------------------------------
#define NX (MROWS * DMODEL)          // 4194304
#define NQ (QKVCOLS * DMODEL)        // 3145728
#define NO (DMODEL * DMODEL)         // 1048576
#define NTOT (NX + NQ + NO)          // 8388608

__global__ void __launch_bounds__(256) round_all_kernel(
    const float* __restrict__ x, const float* __restrict__ wq,
    const float* __restrict__ wo, __half* __restrict__ x16,
    __half* __restrict__ wq16, __half* __restrict__ wo16)
{
    int i = (blockIdx.x * 256 + threadIdx.x) * 4;
    const float* s;
    __half* d;
    if (i < NX)           { s = x  + i;            d = x16  + i; }
    else if (i < NX + NQ) { s = wq + (i - NX);     d = wq16 + (i - NX); }
    else                  { s = wo + (i - NX - NQ); d = wo16 + (i - NX - NQ); }
    float4 v = *(const float4*)s;
    union { __half h[4]; uint2 u; } H = {{__float2half_rn(v.x), __float2half_rn(v.y),
                                          __float2half_rn(v.z), __float2half_rn(v.w)}};
    *(uint2*)d = H.u;
}

// ---------------------------------------------------------------------------
// Fused QK-norm + dilated attention, SMEM-tiled (validated R5-R7).
// ---------------------------------------------------------------------------
#define TI   64
#define WND  (TI + 2 * KOFF * DIL)    // 96
#define ATT_SMEM ((2 * WND * DH + WND) * 4)

__global__ void __launch_bounds__(256, 1) attn_kernel(
    const float* __restrict__ qkv, __half* __restrict__ att)
{
    extern __shared__ float sm[];
    float* ks   = sm;
    float* vs   = sm + WND * DH;
    float* kinv = sm + 2 * WND * DH;

    const int bid = blockIdx.x;
    const int ib = bid & 31;
    const int h  = (bid >> 5) & (HEADS - 1);
    const int b  = bid >> 9;
    const int i0 = ib * TI;
    const int j0 = i0 - KOFF * DIL;

    const int tid  = threadIdx.x;
    const int wid  = tid >> 5;
    const int lane = tid & 31;

    #pragma unroll
    for (int u = tid; u < WND * (DH / 4); u += 256) {
        const int r  = u >> 4;
        const int c4 = (u & 15) * 4;
        const int j  = j0 + r;
        float4 kv4 = make_float4(0.f, 0.f, 0.f, 0.f);
        float4 vv4 = make_float4(0.f, 0.f, 0.f, 0.f);
        if (j >= 0 && j < NTOK) {
            const float* base = qkv + (size_t)(b * NTOK + j) * QKVCOLS + h * DH + c4;
            kv4 = *(const float4*)(base + DMODEL);
            vv4 = *(const float4*)(base + 2 * DMODEL);
        }
        *(float4*)(ks + r * DH + c4) = kv4;
        *(float4*)(vs + r * DH + c4) = vv4;
    }
    __syncthreads();

    for (int r = wid; r < WND; r += 8) {
        const float2 kv = *(const float2*)(ks + r * DH + lane * 2);
        float kk = kv.x * kv.x + kv.y * kv.y;
        #pragma unroll
        for (int m = 16; m >= 1; m >>= 1)
            kk += __shfl_xor_sync(0xffffffffu, kk, m);
        if (lane == 0) kinv[r] = 1.0f / (sqrtf(kk) + EPSN);
    }
    __syncthreads();

    #pragma unroll
    for (int qi = 0; qi < 8; qi++) {
        const int il = wid * 8 + qi;
        const int i  = i0 + il;

        const float2 q = *(const float2*)(
            qkv + (size_t)(b * NTOK + i) * QKVCOLS + h * DH + lane * 2);
        float qq = q.x * q.x + q.y * q.y;
        #pragma unroll
        for (int m = 16; m >= 1; m >>= 1)
            qq += __shfl_xor_sync(0xffffffffu, qq, m);
        const float qinv = 1.0f / (sqrtf(qq) + EPSN);

        float s[NOFF];
        #pragma unroll
        for (int t = 0; t < NOFF; t++) {
            const int j = i + (t - KOFF) * DIL;
            const int r = il + 2 * KOFF + (t - KOFF) * DIL;
            const float2 kv = *(const float2*)(ks + r * DH + lane * 2);
            float p = q.x * kv.x + q.y * kv.y;
            #pragma unroll
            for (int m = 16; m >= 1; m >>= 1)
                p += __shfl_xor_sync(0xffffffffu, p, m);
            s[t] = (j >= 0 && j < NTOK) ? p * qinv * kinv[r] : -1e30f;
        }

        float mx = s[0];
        #pragma unroll
        for (int t = 1; t < NOFF; t++) mx = fmaxf(mx, s[t]);

        float denom = 0.0f;
        #pragma unroll
        for (int t = 0; t < NOFF; t++) { s[t] = __expf(s[t] - mx); denom += s[t]; }
        const float inv = 1.0f / denom;

        float2 acc = make_float2(0.0f, 0.0f);
        #pragma unroll
        for (int t = 0; t < NOFF; t++) {
            const int r = il + 2 * KOFF + (t - KOFF) * DIL;
            const float2 v = *(const float2*)(vs + r * DH + lane * 2);
            const float ww = s[t] * inv;
            acc.x = fmaf(ww, v.x, acc.x);
            acc.y = fmaf(ww, v.y, acc.y);
        }

        const size_t o = (size_t)(b * NTOK + i) * DMODEL + h * DH + lane * 2;
        *(__half2*)(att + o) = __halves2half2(__float2half_rn(acc.x),
                                              __float2half_rn(acc.y));
    }
}

// ---------------------------------------------------------------------------
// Launch
// ---------------------------------------------------------------------------
extern "C" void kernel_launch(void* const* d_in, const int* in_sizes, int n_in,
                              void* d_out, int out_size)
{
    const float* x     = (const float*)d_in[0];
    const float* w_qkv = (const float*)d_in[1];
    const float* b_qkv = (const float*)d_in[2];
    const float* w_out = (const float*)d_in[3];
    const float* b_out = (const float*)d_in[4];
    float* out = (float*)d_out;

    float* qkv;
    __half *x16, *wq16, *wo16, *att16;
    cudaGetSymbolAddress((void**)&qkv,   g_qkv);
    cudaGetSymbolAddress((void**)&x16,   g_x16);
    cudaGetSymbolAddress((void**)&wq16,  g_wq16);
    cudaGetSymbolAddress((void**)&wo16,  g_wo16);
    cudaGetSymbolAddress((void**)&att16, g_att16);

    cudaFuncSetAttribute(gemm_hmma, cudaFuncAttributeMaxDynamicSharedMemorySize,
                         GEMM_SMEM);
    cudaFuncSetAttribute(attn_kernel, cudaFuncAttributeMaxDynamicSharedMemorySize,
                         ATT_SMEM);

    // fp32 -> fp16 rounds (single fused launch)
    round_all_kernel<<<NTOT / 1024, 256>>>(x, w_qkv, w_out, x16, wq16, wo16);

    // 1) QKV projection: [4096, 3072]
    {
        dim3 grid(QKVCOLS / BN, MROWS / BM);   // (12, 32)
        gemm_hmma<<<grid, 256, GEMM_SMEM>>>(x16, wq16, b_qkv, qkv, QKVCOLS);
    }
    // 2) Fused QK-norm + dilated attention (SMEM-tiled, writes fp16)
    attn_kernel<<<BATCH * HEADS * (NTOK / TI), 256, ATT_SMEM>>>(qkv, att16);
    // 3) Output projection: [4096, 1024]
    {
        dim3 grid(DMODEL / BN, MROWS / BM);    // (4, 32)
        gemm_hmma<<<grid, 256, GEMM_SMEM>>>(att16, wo16, b_out, out, DMODEL);
    }
}